// round 1
// baseline (speedup 1.0000x reference)
#include <cuda_runtime.h>
#include <cuda_bf16.h>
#include <math.h>
#include <float.h>

// ---------------- problem constants ----------------
#define V_  4096
#define D_  1024
#define H_  16
#define DH_ 64
#define NL_ 12
#define DFF_ 2752
#define NS_ 6
#define B_  2
#define T_  1365
#define BT_ (B_*T_)          // 2730
#define ZLOSSW 1e-4f

// cumulative scale boundaries: sizes [1,4,16,64,256,1024]
__device__ __constant__ int c_bound[7] = {0, 1, 5, 21, 85, 341, 1365};

// ---------------- scratch (static device globals; no allocs allowed) ----------------
__device__ float g_h[BT_ * D_];
__device__ float g_q[BT_ * D_];
__device__ float g_k[BT_ * D_];
__device__ float g_v[BT_ * D_];
__device__ float g_o[BT_ * D_];
__device__ float g_tmp[BT_ * D_];
__device__ float g_att[(size_t)B_ * H_ * T_ * T_];   // 238 MB
__device__ float g_g1[BT_ * DFF_];
__device__ float g_g3[BT_ * DFF_];
__device__ float g_logits[BT_ * V_];
__device__ int   g_tok[BT_];
__device__ int   g_scl[T_];
__device__ float g_cos[T_ * DH_];
__device__ float g_sin[T_ * DH_];
__device__ float g_ce[BT_];
__device__ float g_zl[BT_];

// ---------------- helpers ----------------
__device__ __forceinline__ void scale_of(int t, int& s, int& p) {
    if (t < 1)        { s = 0; p = t; }
    else if (t < 5)   { s = 1; p = t - 1; }
    else if (t < 21)  { s = 2; p = t - 5; }
    else if (t < 85)  { s = 3; p = t - 21; }
    else if (t < 341) { s = 4; p = t - 85; }
    else              { s = 5; p = t - 341; }
}

__device__ __forceinline__ float blockReduceSum(float v) {
    __shared__ float sm[32];
    __syncthreads();
    int lane = threadIdx.x & 31, w = threadIdx.x >> 5;
    #pragma unroll
    for (int o = 16; o; o >>= 1) v += __shfl_xor_sync(0xffffffffu, v, o);
    if (lane == 0) sm[w] = v;
    __syncthreads();
    int nw = (blockDim.x + 31) >> 5;
    v = (threadIdx.x < nw) ? sm[threadIdx.x] : 0.f;
    if (w == 0) {
        #pragma unroll
        for (int o = 16; o; o >>= 1) v += __shfl_xor_sync(0xffffffffu, v, o);
        if (lane == 0) sm[0] = v;
    }
    __syncthreads();
    return sm[0];
}

__device__ __forceinline__ float blockReduceMax(float v) {
    __shared__ float sm[32];
    __syncthreads();
    int lane = threadIdx.x & 31, w = threadIdx.x >> 5;
    #pragma unroll
    for (int o = 16; o; o >>= 1) v = fmaxf(v, __shfl_xor_sync(0xffffffffu, v, o));
    if (lane == 0) sm[w] = v;
    __syncthreads();
    int nw = (blockDim.x + 31) >> 5;
    v = (threadIdx.x < nw) ? sm[threadIdx.x] : -FLT_MAX;
    if (w == 0) {
        #pragma unroll
        for (int o = 16; o; o >>= 1) v = fmaxf(v, __shfl_xor_sync(0xffffffffu, v, o));
        if (lane == 0) sm[0] = v;
    }
    __syncthreads();
    return sm[0];
}

// ---------------- generic batched SGEMM: C = alpha * A @ op(B) ----------------
// op(B)=B (TB=false, B is KxN) or op(B)=B^T (TB=true, B is NxK)
// batch z: offsets zb=z/hdiv, zh=z%hdiv applied with two stride pairs.
template<bool TB>
__global__ __launch_bounds__(256) void gemm_k(
    const float* __restrict__ A, const float* __restrict__ Bm, float* __restrict__ C,
    int M, int N, int K, int lda, int ldb, int ldc,
    long long sA0, long long sA1, long long sB0, long long sB1,
    long long sC0, long long sC1, int hdiv, float alpha)
{
    int z = blockIdx.z;
    int zb = z / hdiv, zh = z - zb * hdiv;
    A  += zb * sA0 + (long long)zh * sA1;
    Bm += zb * sB0 + (long long)zh * sB1;
    C  += zb * sC0 + (long long)zh * sC1;

    __shared__ float As[16][64];
    __shared__ float Bs[16][64];

    const int tid = threadIdx.x;
    const int tx = tid & 15, ty = tid >> 4;
    const int row0 = blockIdx.y * 64, col0 = blockIdx.x * 64;

    float acc[4][4] = {};

    for (int k0 = 0; k0 < K; k0 += 16) {
        #pragma unroll
        for (int i = 0; i < 4; i++) {
            int e = tid + i * 256;
            int r = e >> 4, kk = e & 15;
            int gr = row0 + r, gk = k0 + kk;
            float v = 0.f;
            if (gr < M && gk < K) v = A[(long long)gr * lda + gk];
            As[kk][r] = v;
        }
        #pragma unroll
        for (int i = 0; i < 4; i++) {
            int e = tid + i * 256;
            float v = 0.f;
            if (!TB) {
                int kk = e >> 6, c = e & 63;
                int gk = k0 + kk, gc = col0 + c;
                if (gk < K && gc < N) v = Bm[(long long)gk * ldb + gc];
                Bs[kk][c] = v;
            } else {
                int c = e >> 4, kk = e & 15;
                int gk = k0 + kk, gc = col0 + c;
                if (gc < N && gk < K) v = Bm[(long long)gc * ldb + gk];
                Bs[kk][c] = v;
            }
        }
        __syncthreads();
        #pragma unroll
        for (int kk = 0; kk < 16; kk++) {
            float a[4], b[4];
            #pragma unroll
            for (int i = 0; i < 4; i++) a[i] = As[kk][ty * 4 + i];
            #pragma unroll
            for (int j = 0; j < 4; j++) b[j] = Bs[kk][tx * 4 + j];
            #pragma unroll
            for (int i = 0; i < 4; i++)
                #pragma unroll
                for (int j = 0; j < 4; j++) acc[i][j] += a[i] * b[j];
        }
        __syncthreads();
    }

    #pragma unroll
    for (int i = 0; i < 4; i++) {
        int gr = row0 + ty * 4 + i;
        if (gr >= M) continue;
        #pragma unroll
        for (int j = 0; j < 4; j++) {
            int gc = col0 + tx * 4 + j;
            if (gc < N) C[(long long)gr * ldc + gc] = alpha * acc[i][j];
        }
    }
}

// ---------------- small kernels ----------------
__global__ void k_static() {
    int t = blockIdx.x;
    int d = threadIdx.x;                  // 64 threads
    int s, p; scale_of(t, s, p);
    if (d == 0) g_scl[t] = s;
    int i = d & 31;
    float inv = powf(10000.f, -(float)(2 * i) / 64.f);
    float ang = (float)p * inv;
    g_cos[t * 64 + d] = cosf(ang);
    g_sin[t * 64 + d] = sinf(ang);
}

__global__ void k_tokens(const int* i0, const int* i1, const int* i2,
                         const int* i3, const int* i4, const int* i5) {
    int idx = blockIdx.x * blockDim.x + threadIdx.x;
    if (idx >= BT_) return;
    int b = idx / T_, t = idx - b * T_;
    int s, p; scale_of(t, s, p);
    const int* arr[6] = {i0, i1, i2, i3, i4, i5};
    int sz = 1 << (2 * s);
    g_tok[idx] = arr[s][b * sz + p];
}

__global__ void k_embed(const float* __restrict__ E, const float* __restrict__ SE,
                        const float* __restrict__ start) {
    int row = blockIdx.x;                  // [0, BT)
    int t = row % T_;
    int s = g_scl[t];
    const float* src = (t == 0) ? start : (E + (long long)g_tok[row] * D_);
    const float* se = SE + s * D_;
    float* hp = g_h + (long long)row * D_;
    for (int d = threadIdx.x; d < D_; d += blockDim.x) hp[d] = src[d] + se[d];
}

// per-head RMSNorm(gain) + RoPE on q and k. grid = BT*H, block = 64 (warp0:q, warp1:k)
__global__ void k_qkrope(const float* __restrict__ qn, const float* __restrict__ kn) {
    int idx = blockIdx.x;
    int head = idx % H_;
    int row = idx / H_;
    int t = row % T_;
    int lane = threadIdx.x & 31;
    bool isK = (threadIdx.x >= 32);
    float* x = (isK ? g_k : g_q) + (long long)row * D_ + head * DH_;
    const float* g = isK ? kn : qn;
    float x1 = x[lane], x2 = x[lane + 32];
    float ss = x1 * x1 + x2 * x2;
    #pragma unroll
    for (int o = 16; o; o >>= 1) ss += __shfl_xor_sync(0xffffffffu, ss, o);
    float r = rsqrtf(ss / 64.f + 1e-6f);
    float y1 = x1 * r * g[lane];
    float y2 = x2 * r * g[lane + 32];
    float c1 = g_cos[t * 64 + lane],      s1 = g_sin[t * 64 + lane];
    float c2 = g_cos[t * 64 + lane + 32], s2 = g_sin[t * 64 + lane + 32];
    x[lane]      = y1 * c1 - y2 * s1;
    x[lane + 32] = y2 * c2 + y1 * s2;
}

// softmax over prefix Li (block-causal mask is a prefix mask since scl is sorted)
__global__ void k_softmax() {
    int r = blockIdx.x;                    // z*T + i, z in [0, B*H)
    int i = r % T_;
    float* row = g_att + (size_t)r * T_;
    int Li = c_bound[g_scl[i] + 1];

    float m = -FLT_MAX;
    for (int j = threadIdx.x; j < Li; j += blockDim.x) m = fmaxf(m, row[j]);
    m = blockReduceMax(m);

    float s = 0.f;
    for (int j = threadIdx.x; j < Li; j += blockDim.x) {
        float e = expf(row[j] - m);
        row[j] = e;
        s += e;
    }
    s = blockReduceSum(s);
    float inv = 1.f / s;
    for (int j = threadIdx.x; j < Li; j += blockDim.x) row[j] *= inv;
    for (int j = Li + threadIdx.x; j < T_; j += blockDim.x) row[j] = 0.f;
}

// h = RMSNorm(h + delta) * gain   (eps inside mean, matching reference)
__global__ void k_rms(float* __restrict__ h, const float* __restrict__ delta,
                      const float* __restrict__ gain) {
    int row = blockIdx.x;
    float* hp = h + (long long)row * D_;
    const float* dp = delta + (long long)row * D_;
    float ss = 0.f;
    for (int d = threadIdx.x; d < D_; d += blockDim.x) {
        float x = hp[d] + dp[d];
        ss += x * x;
    }
    ss = blockReduceSum(ss);
    float r = rsqrtf(ss / (float)D_ + 1e-6f);
    for (int d = threadIdx.x; d < D_; d += blockDim.x) {
        float x = hp[d] + dp[d];
        hp[d] = x * r * gain[d];
    }
}

__global__ void k_silu() {
    long long i = (long long)blockIdx.x * blockDim.x + threadIdx.x;
    if (i >= (long long)BT_ * DFF_) return;
    float a = g_g1[i];
    g_g1[i] = a / (1.f + expf(-a)) * g_g3[i];
}

__global__ void k_loss_row() {
    int row = blockIdx.x;
    const float* lp = g_logits + (size_t)row * V_;
    float m = -FLT_MAX;
    for (int j = threadIdx.x; j < V_; j += blockDim.x) m = fmaxf(m, lp[j]);
    m = blockReduceMax(m);
    float s = 0.f;
    for (int j = threadIdx.x; j < V_; j += blockDim.x) s += expf(lp[j] - m);
    s = blockReduceSum(s);
    if (threadIdx.x == 0) {
        float lse = m + logf(s);
        g_ce[row] = lse - lp[g_tok[row]];
        g_zl[row] = lse * lse;
    }
}

__global__ void k_loss_final(float* out) {
    float s1 = 0.f, s2 = 0.f;
    for (int j = threadIdx.x; j < BT_; j += blockDim.x) { s1 += g_ce[j]; s2 += g_zl[j]; }
    s1 = blockReduceSum(s1);
    s2 = blockReduceSum(s2);
    if (threadIdx.x == 0) out[0] = s1 / (float)BT_ + ZLOSSW * (s2 / (float)BT_);
}

// ---------------- host-side GEMM helper ----------------
static inline void launch_gemm(bool tb,
    const float* A, const float* B, float* C,
    int M, int N, int K, int lda, int ldb, int ldc,
    long long sA0, long long sA1, long long sB0, long long sB1,
    long long sC0, long long sC1, int batches, int hdiv, float alpha)
{
    dim3 grid((N + 63) / 64, (M + 63) / 64, batches);
    if (tb)
        gemm_k<true><<<grid, 256>>>(A, B, C, M, N, K, lda, ldb, ldc,
                                    sA0, sA1, sB0, sB1, sC0, sC1, hdiv, alpha);
    else
        gemm_k<false><<<grid, 256>>>(A, B, C, M, N, K, lda, ldb, ldc,
                                     sA0, sA1, sB0, sB1, sC0, sC1, hdiv, alpha);
}

// ---------------- entry point ----------------
extern "C" void kernel_launch(void* const* d_in, const int* in_sizes, int n_in,
                              void* d_out, int out_size) {
    const int* i0 = (const int*)d_in[0];
    const int* i1 = (const int*)d_in[1];
    const int* i2 = (const int*)d_in[2];
    const int* i3 = (const int*)d_in[3];
    const int* i4 = (const int*)d_in[4];
    const int* i5 = (const int*)d_in[5];
    const float* token_embed = (const float*)d_in[6];
    const float* scale_embed = (const float*)d_in[7];
    const float* start_token = (const float*)d_in[8];
    const float* wq = (const float*)d_in[9];
    const float* wk = (const float*)d_in[10];
    const float* wv = (const float*)d_in[11];
    const float* wo = (const float*)d_in[12];
    const float* qn = (const float*)d_in[13];
    const float* kn = (const float*)d_in[14];
    const float* n1 = (const float*)d_in[15];
    const float* n2 = (const float*)d_in[16];
    const float* w1 = (const float*)d_in[17];
    const float* w3 = (const float*)d_in[18];
    const float* w2 = (const float*)d_in[19];

    void* p;
    cudaGetSymbolAddress(&p, g_h);      float* h   = (float*)p;
    cudaGetSymbolAddress(&p, g_q);      float* q   = (float*)p;
    cudaGetSymbolAddress(&p, g_k);      float* k   = (float*)p;
    cudaGetSymbolAddress(&p, g_v);      float* v   = (float*)p;
    cudaGetSymbolAddress(&p, g_o);      float* o   = (float*)p;
    cudaGetSymbolAddress(&p, g_tmp);    float* tmp = (float*)p;
    cudaGetSymbolAddress(&p, g_att);    float* att = (float*)p;
    cudaGetSymbolAddress(&p, g_g1);     float* gg  = (float*)p;
    cudaGetSymbolAddress(&p, g_g3);     float* uu  = (float*)p;
    cudaGetSymbolAddress(&p, g_logits); float* lg  = (float*)p;

    // static tables + embeddings
    k_static<<<T_, 64>>>();
    k_tokens<<<(BT_ + 255) / 256, 256>>>(i0, i1, i2, i3, i4, i5);
    k_embed<<<BT_, 256>>>(token_embed, scale_embed, start_token);

    const long long DD = (long long)D_ * D_;

    for (int l = 0; l < NL_; l++) {
        // q, k, v projections: [BT, D] @ [D, D]
        launch_gemm(false, h, wq + l * DD, q, BT_, D_, D_, D_, D_, D_,
                    0, 0, 0, 0, 0, 0, 1, 1, 1.f);
        launch_gemm(false, h, wk + l * DD, k, BT_, D_, D_, D_, D_, D_,
                    0, 0, 0, 0, 0, 0, 1, 1, 1.f);
        launch_gemm(false, h, wv + l * DD, v, BT_, D_, D_, D_, D_, D_,
                    0, 0, 0, 0, 0, 0, 1, 1, 1.f);

        // QK-norm + RoPE
        k_qkrope<<<BT_ * H_, 64>>>(qn + l * DH_, kn + l * DH_);

        // scores = q @ k^T * (1/8), batched over (b, head)
        launch_gemm(true, q, k, att, T_, T_, DH_, D_, D_, T_,
                    (long long)T_ * D_, DH_,
                    (long long)T_ * D_, DH_,
                    (long long)H_ * T_ * T_, (long long)T_ * T_,
                    B_ * H_, H_, 0.125f);

        // prefix-masked softmax
        k_softmax<<<B_ * H_ * T_, 256>>>();

        // o_head = p @ v_head  (writes head slices back into [BT, D])
        launch_gemm(false, att, v, o, T_, DH_, T_, T_, D_, D_,
                    (long long)H_ * T_ * T_, (long long)T_ * T_,
                    (long long)T_ * D_, DH_,
                    (long long)T_ * D_, DH_,
                    B_ * H_, H_, 1.f);

        // attn output projection
        launch_gemm(false, o, wo + l * DD, tmp, BT_, D_, D_, D_, D_, D_,
                    0, 0, 0, 0, 0, 0, 1, 1, 1.f);

        // h = rms(h + attn) * n1
        k_rms<<<BT_, 256>>>(h, tmp, n1 + l * D_);

        // FFN: gg = h@w1, uu = h@w3, gg = silu(gg)*uu, tmp = gg@w2
        launch_gemm(false, h, w1 + (long long)l * D_ * DFF_, gg, BT_, DFF_, D_,
                    D_, DFF_, DFF_, 0, 0, 0, 0, 0, 0, 1, 1, 1.f);
        launch_gemm(false, h, w3 + (long long)l * D_ * DFF_, uu, BT_, DFF_, D_,
                    D_, DFF_, DFF_, 0, 0, 0, 0, 0, 0, 1, 1, 1.f);
        {
            long long n = (long long)BT_ * DFF_;
            k_silu<<<(unsigned)((n + 255) / 256), 256>>>();
        }
        launch_gemm(false, gg, w2 + (long long)l * DFF_ * D_, tmp, BT_, D_, DFF_,
                    DFF_, D_, D_, 0, 0, 0, 0, 0, 0, 1, 1, 1.f);

        // h = rms(h + ffn) * n2
        k_rms<<<BT_, 256>>>(h, tmp, n2 + l * D_);
    }

    // logits = h @ token_embed^T
    launch_gemm(true, h, token_embed, lg, BT_, V_, D_, D_, D_, V_,
                0, 0, 0, 0, 0, 0, 1, 1, 1.f);

    // loss
    k_loss_row<<<BT_, 256>>>();
    k_loss_final<<<1, 256>>>((float*)d_out);
}

// round 3
// speedup vs baseline: 1.8327x; 1.8327x over previous
#include <cuda_runtime.h>
#include <cuda_bf16.h>
#include <math.h>
#include <float.h>

// ---------------- problem constants ----------------
#define V_  4096
#define D_  1024
#define H_  16
#define DH_ 64
#define NL_ 12
#define DFF_ 2752
#define NS_ 6
#define B_  2
#define T_  1365
#define BT_ (B_*T_)          // 2730
#define ZLOSSW 1e-4f

// cumulative scale boundaries: sizes [1,4,16,64,256,1024]
__device__ __constant__ int c_bound[7] = {0, 1, 5, 21, 85, 341, 1365};

// ---------------- scratch (static device globals; no allocs allowed) ----------------
__device__ float g_h[BT_ * D_];
__device__ float g_qkv[3 * BT_ * D_];
__device__ float g_o[BT_ * D_];
__device__ float g_tmp[BT_ * D_];
__device__ float g_att[(size_t)B_ * H_ * T_ * T_];   // 238 MB
__device__ float g_ffn[2 * (size_t)BT_ * DFF_];
__device__ float g_logits[(size_t)BT_ * V_];
__device__ int   g_tok[BT_];
__device__ int   g_scl[T_];
__device__ float g_cos[T_ * DH_];
__device__ float g_sin[T_ * DH_];
__device__ float g_ce[BT_];
__device__ float g_zl[BT_];

// ---------------- helpers ----------------
__device__ __forceinline__ void scale_of(int t, int& s, int& p) {
    if (t < 1)        { s = 0; p = t; }
    else if (t < 5)   { s = 1; p = t - 1; }
    else if (t < 21)  { s = 2; p = t - 5; }
    else if (t < 85)  { s = 3; p = t - 21; }
    else if (t < 341) { s = 4; p = t - 85; }
    else              { s = 5; p = t - 341; }
}

__device__ __forceinline__ float tf32r(float x) {
    unsigned u;
    asm("cvt.rna.tf32.f32 %0, %1;" : "=r"(u) : "f"(x));
    return __uint_as_float(u);
}

__device__ __forceinline__ float blockReduceSum(float v) {
    __shared__ float sm[32];
    __syncthreads();
    int lane = threadIdx.x & 31, w = threadIdx.x >> 5;
    #pragma unroll
    for (int o = 16; o; o >>= 1) v += __shfl_xor_sync(0xffffffffu, v, o);
    if (lane == 0) sm[w] = v;
    __syncthreads();
    int nw = (blockDim.x + 31) >> 5;
    v = (threadIdx.x < nw) ? sm[threadIdx.x] : 0.f;
    if (w == 0) {
        #pragma unroll
        for (int o = 16; o; o >>= 1) v += __shfl_xor_sync(0xffffffffu, v, o);
        if (lane == 0) sm[0] = v;
    }
    __syncthreads();
    return sm[0];
}

__device__ __forceinline__ float blockReduceMax(float v) {
    __shared__ float sm[32];
    __syncthreads();
    int lane = threadIdx.x & 31, w = threadIdx.x >> 5;
    #pragma unroll
    for (int o = 16; o; o >>= 1) v = fmaxf(v, __shfl_xor_sync(0xffffffffu, v, o));
    if (lane == 0) sm[w] = v;
    __syncthreads();
    int nw = (blockDim.x + 31) >> 5;
    v = (threadIdx.x < nw) ? sm[threadIdx.x] : -FLT_MAX;
    if (w == 0) {
        #pragma unroll
        for (int o = 16; o; o >>= 1) v = fmaxf(v, __shfl_xor_sync(0xffffffffu, v, o));
        if (lane == 0) sm[0] = v;
    }
    __syncthreads();
    return sm[0];
}

#define MMA_TF32(d, a, b) asm volatile( \
  "mma.sync.aligned.m16n8k8.row.col.f32.tf32.tf32.f32 " \
  "{%0,%1,%2,%3},{%4,%5,%6,%7},{%8,%9},{%0,%1,%2,%3};\n" \
  : "+f"(d[0]), "+f"(d[1]), "+f"(d[2]), "+f"(d[3]) \
  : "r"(__float_as_uint(a[0])), "r"(__float_as_uint(a[1])), \
    "r"(__float_as_uint(a[2])), "r"(__float_as_uint(a[3])), \
    "r"(__float_as_uint(b[0])), "r"(__float_as_uint(b[1])))

// ---------------- TF32 tensor-core GEMM ----------------
// C = alpha * A @ op(B). Tiles: BM=128 x BN(128|64) x BK=16, 256 threads, 8 warps (4Mx2N).
// Batch z: zb=z/hdiv, zh=z%hdiv; A/C strided. B: if B1 != nullptr, select {B0,B1,B2} by z,
// else B0 strided like A.
// limMode: 0=none, 1=clamp K to prefix bound of this row block (P@V),
//          2=skip block if col0 >= prefix bound (QK^T).
template<int BN, bool TB>
__global__ __launch_bounds__(256) void gemm_tc(
    const float* __restrict__ A, const float* __restrict__ B0,
    const float* __restrict__ B1, const float* __restrict__ B2,
    float* __restrict__ C,
    int M, int N, int K, int lda, int ldb, int ldc,
    long long sA0, long long sA1, long long sB0, long long sB1,
    long long sC0, long long sC1, int hdiv, float alpha, int limMode)
{
    constexpr int BM = 128, BK = 16;
    constexpr int NI = BN / 16;            // mma n-tiles per warp (8 or 4)

    const int z = blockIdx.z;
    const int zb = z / hdiv, zh = z - zb * hdiv;
    const float* Bm;
    if (B1 != nullptr) Bm = (z == 0) ? B0 : ((z == 1) ? B1 : B2);
    else               Bm = B0 + zb * sB0 + (long long)zh * sB1;
    A += zb * sA0 + (long long)zh * sA1;
    C += zb * sC0 + (long long)zh * sC1;

    const int row0 = blockIdx.y * BM, col0 = blockIdx.x * BN;

    int Kend = K;
    if (limMode) {
        int lr = min(row0 + BM - 1, M - 1);
        int s, pp; scale_of(lr, s, pp);
        int Lmax = c_bound[s + 1];
        if (limMode == 2 && col0 >= Lmax) return;
        if (limMode == 1) Kend = min(K, Lmax);
    }

    __shared__ float As[BK][BM + 4];
    __shared__ float Bs[BK][BN + 4];

    const int tid = threadIdx.x;
    const int lane = tid & 31, warp = tid >> 5;
    const int wm = warp >> 1, wn = warp & 1;

    float acc[2][NI][4] = {};

    // ---- load mappings ----
    const int arow = tid >> 1, ak0 = (tid & 1) * 8;   // A: 128 rows x 2 threads x 8k
    float ra[8], rb[8];

    const int agr = row0 + arow;
    const bool arok = agr < M;
    const float* aRow = A + (long long)agr * lda;

    // B mapping precompute
    int b_kk = 0, b_c4 = 0, b_col = 0, b_kb = 0;
    bool bcok = true;
    if (!TB) {
        if (BN == 128) { b_kk = tid >> 5; b_c4 = (tid & 31) * 4; }
        else           { b_kk = tid >> 4; b_c4 = (tid & 15) * 4; }
    } else {
        if (BN == 128) { b_col = tid >> 1; b_kb = (tid & 1) * 8; }
        else           { b_col = tid >> 2; b_kb = (tid & 3) * 4; }
        bcok = (col0 + b_col) < N;
    }

    // NOTE: loads are guarded with Kend (not K): when Kend is a prefix bound
    // (limMode=1) it is NOT a multiple of BK, and the region [Kend, ceil16(Kend))
    // of A holds un-softmaxed garbage. Zero-pad the partial tile.
    auto loadA = [&](int k0) {
        #pragma unroll
        for (int j = 0; j < 8; j++) {
            int gk = k0 + ak0 + j;
            ra[j] = (arok && gk < Kend) ? aRow[gk] : 0.f;
        }
    };
    auto loadB = [&](int k0) {
        if (!TB) {
            if (BN == 128) {
                #pragma unroll
                for (int i = 0; i < 2; i++) {
                    int gk = k0 + b_kk + i * 8;
                    bool kok = gk < Kend;
                    const float* bp = Bm + (long long)gk * ldb + col0 + b_c4;
                    #pragma unroll
                    for (int j = 0; j < 4; j++) {
                        int gc = col0 + b_c4 + j;
                        rb[i * 4 + j] = (kok && gc < N) ? bp[j] : 0.f;
                    }
                }
            } else {
                int gk = k0 + b_kk;
                bool kok = gk < Kend;
                const float* bp = Bm + (long long)gk * ldb + col0 + b_c4;
                #pragma unroll
                for (int j = 0; j < 4; j++) {
                    int gc = col0 + b_c4 + j;
                    rb[j] = (kok && gc < N) ? bp[j] : 0.f;
                }
            }
        } else {
            const float* bp = Bm + (long long)(col0 + b_col) * ldb + k0 + b_kb;
            constexpr int NE = (BN == 128) ? 8 : 4;
            #pragma unroll
            for (int j = 0; j < NE; j++) {
                int gk = k0 + b_kb + j;
                rb[j] = (bcok && gk < Kend) ? bp[j] : 0.f;
            }
        }
    };
    auto storeAB = [&]() {
        #pragma unroll
        for (int j = 0; j < 8; j++) As[ak0 + j][arow] = tf32r(ra[j]);
        if (!TB) {
            if (BN == 128) {
                #pragma unroll
                for (int i = 0; i < 2; i++)
                    #pragma unroll
                    for (int j = 0; j < 4; j++)
                        Bs[b_kk + i * 8][b_c4 + j] = tf32r(rb[i * 4 + j]);
            } else {
                #pragma unroll
                for (int j = 0; j < 4; j++) Bs[b_kk][b_c4 + j] = tf32r(rb[j]);
            }
        } else {
            constexpr int NE = (BN == 128) ? 8 : 4;
            #pragma unroll
            for (int j = 0; j < NE; j++) Bs[b_kb + j][b_col] = tf32r(rb[j]);
        }
    };

    loadA(0); loadB(0);

    const int gr = lane >> 2, gc = lane & 3;

    for (int k0 = 0; k0 < Kend; k0 += BK) {
        storeAB();
        __syncthreads();
        int kn = k0 + BK;
        if (kn < Kend) { loadA(kn); loadB(kn); }

        #pragma unroll
        for (int ks = 0; ks < 2; ks++) {
            int kb = ks * 8;
            float a[2][4];
            #pragma unroll
            for (int mi = 0; mi < 2; mi++) {
                int m0 = wm * 32 + mi * 16;
                a[mi][0] = As[kb + gc][m0 + gr];
                a[mi][1] = As[kb + gc][m0 + gr + 8];
                a[mi][2] = As[kb + gc + 4][m0 + gr];
                a[mi][3] = As[kb + gc + 4][m0 + gr + 8];
            }
            float b[NI][2];
            #pragma unroll
            for (int ni = 0; ni < NI; ni++) {
                int n0 = wn * (BN / 2) + ni * 8;
                b[ni][0] = Bs[kb + gc][n0 + gr];
                b[ni][1] = Bs[kb + gc + 4][n0 + gr];
            }
            #pragma unroll
            for (int mi = 0; mi < 2; mi++)
                #pragma unroll
                for (int ni = 0; ni < NI; ni++)
                    MMA_TF32(acc[mi][ni], a[mi], b[ni]);
        }
        __syncthreads();
    }

    // epilogue
    #pragma unroll
    for (int mi = 0; mi < 2; mi++) {
        int r = row0 + wm * 32 + mi * 16 + gr;
        #pragma unroll
        for (int ni = 0; ni < NI; ni++) {
            int c = col0 + wn * (BN / 2) + ni * 8 + gc * 2;
            float* cp = C + (long long)r * ldc + c;
            if (r < M) {
                if (c < N)     cp[0] = alpha * acc[mi][ni][0];
                if (c + 1 < N) cp[1] = alpha * acc[mi][ni][1];
            }
            if (r + 8 < M) {
                if (c < N)     cp[(long long)8 * ldc]     = alpha * acc[mi][ni][2];
                if (c + 1 < N) cp[(long long)8 * ldc + 1] = alpha * acc[mi][ni][3];
            }
        }
    }
}

// ---------------- small kernels ----------------
__global__ void k_static() {
    int t = blockIdx.x;
    int d = threadIdx.x;                  // 64 threads
    int s, p; scale_of(t, s, p);
    if (d == 0) g_scl[t] = s;
    int i = d & 31;
    float inv = powf(10000.f, -(float)(2 * i) / 64.f);
    float ang = (float)p * inv;
    g_cos[t * 64 + d] = cosf(ang);
    g_sin[t * 64 + d] = sinf(ang);
}

__global__ void k_tokens(const int* i0, const int* i1, const int* i2,
                         const int* i3, const int* i4, const int* i5) {
    int idx = blockIdx.x * blockDim.x + threadIdx.x;
    if (idx >= BT_) return;
    int b = idx / T_, t = idx - b * T_;
    int s, p; scale_of(t, s, p);
    const int* arr[6] = {i0, i1, i2, i3, i4, i5};
    int sz = 1 << (2 * s);
    g_tok[idx] = arr[s][b * sz + p];
}

__global__ void k_embed(const float* __restrict__ E, const float* __restrict__ SE,
                        const float* __restrict__ start) {
    int row = blockIdx.x;                  // [0, BT)
    int t = row % T_;
    int s = g_scl[t];
    const float* src = (t == 0) ? start : (E + (long long)g_tok[row] * D_);
    const float* se = SE + s * D_;
    float* hp = g_h + (long long)row * D_;
    for (int d = threadIdx.x; d < D_; d += blockDim.x) hp[d] = src[d] + se[d];
}

// per-head RMSNorm(gain) + RoPE on q and k. grid = BT*H, block = 64 (warp0:q, warp1:k)
__global__ void k_qkrope(const float* __restrict__ qn, const float* __restrict__ kn) {
    int idx = blockIdx.x;
    int head = idx % H_;
    int row = idx / H_;
    int t = row % T_;
    int lane = threadIdx.x & 31;
    bool isK = (threadIdx.x >= 32);
    float* x = g_qkv + (isK ? (long long)BT_ * D_ : 0) + (long long)row * D_ + head * DH_;
    const float* g = isK ? kn : qn;
    float x1 = x[lane], x2 = x[lane + 32];
    float ss = x1 * x1 + x2 * x2;
    #pragma unroll
    for (int o = 16; o; o >>= 1) ss += __shfl_xor_sync(0xffffffffu, ss, o);
    float r = rsqrtf(ss / 64.f + 1e-6f);
    float y1 = x1 * r * g[lane];
    float y2 = x2 * r * g[lane + 32];
    float c1 = g_cos[t * 64 + lane],      s1 = g_sin[t * 64 + lane];
    float c2 = g_cos[t * 64 + lane + 32], s2 = g_sin[t * 64 + lane + 32];
    x[lane]      = y1 * c1 - y2 * s1;
    x[lane + 32] = y2 * c2 + y1 * s2;
}

// softmax over prefix Li; zero-fill only up to the 128-row block's prefix bound
// (the P@V gemm clamps its K loop to the same bound and zero-pads partial tiles).
__global__ void k_softmax() {
    int r = blockIdx.x;                    // z*T + i, z in [0, B*H)
    int i = r % T_;
    float* row = g_att + (size_t)r * T_;
    int Li = c_bound[g_scl[i] + 1];
    int blast = min((i >> 7) * 128 + 127, T_ - 1);
    int Lz = c_bound[g_scl[blast] + 1];

    float m = -FLT_MAX;
    for (int j = threadIdx.x; j < Li; j += blockDim.x) m = fmaxf(m, row[j]);
    m = blockReduceMax(m);

    float s = 0.f;
    for (int j = threadIdx.x; j < Li; j += blockDim.x) {
        float e = expf(row[j] - m);
        row[j] = e;
        s += e;
    }
    s = blockReduceSum(s);
    float inv = 1.f / s;
    for (int j = threadIdx.x; j < Li; j += blockDim.x) row[j] *= inv;
    for (int j = Li + threadIdx.x; j < Lz; j += blockDim.x) row[j] = 0.f;
}

// h = RMSNorm(h + delta) * gain
__global__ void k_rms(float* __restrict__ h, const float* __restrict__ delta,
                      const float* __restrict__ gain) {
    int row = blockIdx.x;
    float* hp = h + (long long)row * D_;
    const float* dp = delta + (long long)row * D_;
    float ss = 0.f;
    for (int d = threadIdx.x; d < D_; d += blockDim.x) {
        float x = hp[d] + dp[d];
        ss += x * x;
    }
    ss = blockReduceSum(ss);
    float r = rsqrtf(ss / (float)D_ + 1e-6f);
    for (int d = threadIdx.x; d < D_; d += blockDim.x) {
        float x = hp[d] + dp[d];
        hp[d] = x * r * gain[d];
    }
}

__global__ void k_silu() {
    long long i = (long long)blockIdx.x * blockDim.x + threadIdx.x;
    if (i >= (long long)BT_ * DFF_) return;
    float a = g_ffn[i];
    g_ffn[i] = a / (1.f + expf(-a)) * g_ffn[(long long)BT_ * DFF_ + i];
}

__global__ void k_loss_row() {
    int row = blockIdx.x;
    const float* lp = g_logits + (size_t)row * V_;
    float m = -FLT_MAX;
    for (int j = threadIdx.x; j < V_; j += blockDim.x) m = fmaxf(m, lp[j]);
    m = blockReduceMax(m);
    float s = 0.f;
    for (int j = threadIdx.x; j < V_; j += blockDim.x) s += expf(lp[j] - m);
    s = blockReduceSum(s);
    if (threadIdx.x == 0) {
        float lse = m + logf(s);
        g_ce[row] = lse - lp[g_tok[row]];
        g_zl[row] = lse * lse;
    }
}

__global__ void k_loss_final(float* out) {
    float s1 = 0.f, s2 = 0.f;
    for (int j = threadIdx.x; j < BT_; j += blockDim.x) { s1 += g_ce[j]; s2 += g_zl[j]; }
    s1 = blockReduceSum(s1);
    s2 = blockReduceSum(s2);
    if (threadIdx.x == 0) out[0] = s1 / (float)BT_ + ZLOSSW * (s2 / (float)BT_);
}

// ---------------- entry point ----------------
extern "C" void kernel_launch(void* const* d_in, const int* in_sizes, int n_in,
                              void* d_out, int out_size) {
    const int* i0 = (const int*)d_in[0];
    const int* i1 = (const int*)d_in[1];
    const int* i2 = (const int*)d_in[2];
    const int* i3 = (const int*)d_in[3];
    const int* i4 = (const int*)d_in[4];
    const int* i5 = (const int*)d_in[5];
    const float* token_embed = (const float*)d_in[6];
    const float* scale_embed = (const float*)d_in[7];
    const float* start_token = (const float*)d_in[8];
    const float* wq = (const float*)d_in[9];
    const float* wk = (const float*)d_in[10];
    const float* wv = (const float*)d_in[11];
    const float* wo = (const float*)d_in[12];
    const float* qn = (const float*)d_in[13];
    const float* kn = (const float*)d_in[14];
    const float* n1 = (const float*)d_in[15];
    const float* n2 = (const float*)d_in[16];
    const float* w1 = (const float*)d_in[17];
    const float* w3 = (const float*)d_in[18];
    const float* w2 = (const float*)d_in[19];

    void* p;
    cudaGetSymbolAddress(&p, g_h);      float* h   = (float*)p;
    cudaGetSymbolAddress(&p, g_qkv);    float* qkv = (float*)p;
    cudaGetSymbolAddress(&p, g_o);      float* o   = (float*)p;
    cudaGetSymbolAddress(&p, g_tmp);    float* tmp = (float*)p;
    cudaGetSymbolAddress(&p, g_att);    float* att = (float*)p;
    cudaGetSymbolAddress(&p, g_ffn);    float* ffn = (float*)p;
    cudaGetSymbolAddress(&p, g_logits); float* lg  = (float*)p;

    float* q = qkv;
    float* k = qkv + (long long)BT_ * D_;
    float* v = qkv + 2LL * BT_ * D_;
    float* gg = ffn;

    // static tables + embeddings
    k_static<<<T_, 64>>>();
    k_tokens<<<(BT_ + 255) / 256, 256>>>(i0, i1, i2, i3, i4, i5);
    k_embed<<<BT_, 256>>>(token_embed, scale_embed, start_token);

    const long long DD = (long long)D_ * D_;
    const long long TD = (long long)T_ * D_;
    const long long TT = (long long)T_ * T_;

    const int MB = (BT_ + 127) / 128;       // 22
    const int TBk = (T_ + 127) / 128;       // 11

    for (int l = 0; l < NL_; l++) {
        // fused qkv: z selects wq/wk/wv, C strided into q/k/v slabs
        gemm_tc<128, false><<<dim3(D_ / 128, MB, 3), 256>>>(
            h, wq + l * DD, wk + l * DD, wv + l * DD, qkv,
            BT_, D_, D_, D_, D_, D_,
            0, 0, 0, 0, (long long)BT_ * D_, 0, 1, 1.f, 0);

        k_qkrope<<<BT_ * H_, 64>>>(qn + l * DH_, kn + l * DH_);

        // scores = q @ k^T / 8, batched over (b, head); skip blocks past prefix bound
        gemm_tc<128, true><<<dim3(TBk, TBk, B_ * H_), 256>>>(
            q, k, nullptr, nullptr, att,
            T_, T_, DH_, D_, D_, T_,
            TD, DH_, TD, DH_, (long long)H_ * TT, TT, H_, 0.125f, 2);

        k_softmax<<<B_ * H_ * T_, 256>>>();

        // o_head = p @ v_head; K-loop clamped to prefix bound (zero-padded partial tile)
        gemm_tc<64, false><<<dim3(1, TBk, B_ * H_), 256>>>(
            att, v, nullptr, nullptr, o,
            T_, DH_, T_, T_, D_, D_,
            (long long)H_ * TT, TT, TD, DH_, TD, DH_, H_, 1.f, 1);

        // attn output projection
        gemm_tc<128, false><<<dim3(D_ / 128, MB, 1), 256>>>(
            o, wo + l * DD, nullptr, nullptr, tmp,
            BT_, D_, D_, D_, D_, D_,
            0, 0, 0, 0, 0, 0, 1, 1.f, 0);

        k_rms<<<BT_, 256>>>(h, tmp, n1 + l * D_);

        // fused w1/w3 (z selects weight, C strided into gg/uu slabs)
        gemm_tc<128, false><<<dim3((DFF_ + 127) / 128, MB, 2), 256>>>(
            h, w1 + (long long)l * D_ * DFF_, w3 + (long long)l * D_ * DFF_, nullptr, ffn,
            BT_, DFF_, D_, D_, DFF_, DFF_,
            0, 0, 0, 0, (long long)BT_ * DFF_, 0, 1, 1.f, 0);

        {
            long long n = (long long)BT_ * DFF_;
            k_silu<<<(unsigned)((n + 255) / 256), 256>>>();
        }

        gemm_tc<128, false><<<dim3(D_ / 128, MB, 1), 256>>>(
            gg, w2 + (long long)l * DFF_ * D_, nullptr, nullptr, tmp,
            BT_, D_, DFF_, DFF_, D_, D_,
            0, 0, 0, 0, 0, 0, 1, 1.f, 0);

        k_rms<<<BT_, 256>>>(h, tmp, n2 + l * D_);
    }

    // logits = h @ token_embed^T
    gemm_tc<128, true><<<dim3(V_ / 128, MB, 1), 256>>>(
        h, token_embed, nullptr, nullptr, lg,
        BT_, V_, D_, D_, D_, V_,
        0, 0, 0, 0, 0, 0, 1, 1.f, 0);

    // loss
    k_loss_row<<<BT_, 256>>>();
    k_loss_final<<<1, 256>>>((float*)d_out);
}

// round 4
// speedup vs baseline: 5.7376x; 3.1307x over previous
#include <cuda_runtime.h>
#include <cuda_bf16.h>
#include <math.h>
#include <float.h>

// ---------------- problem constants ----------------
#define V_  4096
#define D_  1024
#define H_  16
#define DH_ 64
#define NL_ 12
#define DFF_ 2752
#define B_  2
#define T_  1365
#define BT_ (B_*T_)          // 2730
#define LDT 1376             // T padded to multiple of 16 (32B rows for bf16)
#define ZLOSSW 1e-4f

typedef __nv_bfloat16 bf16;

__device__ __constant__ int c_bound[7] = {0, 1, 5, 21, 85, 341, 1365};

// ---------------- scratch (static device globals) ----------------
__device__ float g_h[BT_ * D_];
__device__ float g_qkv[3 * BT_ * D_];
__device__ float g_tmp[BT_ * D_];
__device__ float g_att[(size_t)B_ * H_ * T_ * LDT];     // fp32 scores
__device__ float g_logits[(size_t)BT_ * V_];
__device__ float g_ce[BT_];
__device__ float g_zl[BT_];
__device__ int   g_tok[BT_];
__device__ int   g_scl[T_];
__device__ float g_cos[T_ * DH_];
__device__ float g_sin[T_ * DH_];

// bf16 operands
__device__ bf16 g_hb[BT_ * D_];
__device__ bf16 g_qb[BT_ * D_];
__device__ bf16 g_kb[BT_ * D_];
__device__ bf16 g_vt[(size_t)B_ * D_ * LDT];            // [b][d=h*64+dh][t] transposed V
__device__ bf16 g_ob[BT_ * D_];
__device__ bf16 g_attb[(size_t)B_ * H_ * T_ * LDT];     // bf16 probs
__device__ bf16 g_ggb[(size_t)BT_ * DFF_];
// transposed bf16 weights ([N][K] layout for the GEMM B operand)
__device__ bf16 g_wqt[NL_ * D_ * D_];
__device__ bf16 g_wkt[NL_ * D_ * D_];
__device__ bf16 g_wvt[NL_ * D_ * D_];
__device__ bf16 g_wot[NL_ * D_ * D_];
__device__ bf16 g_w1t[(size_t)NL_ * DFF_ * D_];
__device__ bf16 g_w3t[(size_t)NL_ * DFF_ * D_];
__device__ bf16 g_w2t[(size_t)NL_ * D_ * DFF_];
__device__ bf16 g_embb[V_ * D_];

// ---------------- helpers ----------------
__device__ __forceinline__ void scale_of(int t, int& s, int& p) {
    if (t < 1)        { s = 0; p = t; }
    else if (t < 5)   { s = 1; p = t - 1; }
    else if (t < 21)  { s = 2; p = t - 5; }
    else if (t < 85)  { s = 3; p = t - 21; }
    else if (t < 341) { s = 4; p = t - 85; }
    else              { s = 5; p = t - 341; }
}

__device__ __forceinline__ float blockReduceSum(float v) {
    __shared__ float sm[32];
    __syncthreads();
    int lane = threadIdx.x & 31, w = threadIdx.x >> 5;
    #pragma unroll
    for (int o = 16; o; o >>= 1) v += __shfl_xor_sync(0xffffffffu, v, o);
    if (lane == 0) sm[w] = v;
    __syncthreads();
    int nw = (blockDim.x + 31) >> 5;
    v = (threadIdx.x < nw) ? sm[threadIdx.x] : 0.f;
    if (w == 0) {
        #pragma unroll
        for (int o = 16; o; o >>= 1) v += __shfl_xor_sync(0xffffffffu, v, o);
        if (lane == 0) sm[0] = v;
    }
    __syncthreads();
    return sm[0];
}

__device__ __forceinline__ float blockReduceMax(float v) {
    __shared__ float sm[32];
    __syncthreads();
    int lane = threadIdx.x & 31, w = threadIdx.x >> 5;
    #pragma unroll
    for (int o = 16; o; o >>= 1) v = fmaxf(v, __shfl_xor_sync(0xffffffffu, v, o));
    if (lane == 0) sm[w] = v;
    __syncthreads();
    int nw = (blockDim.x + 31) >> 5;
    v = (threadIdx.x < nw) ? sm[threadIdx.x] : -FLT_MAX;
    if (w == 0) {
        #pragma unroll
        for (int o = 16; o; o >>= 1) v = fmaxf(v, __shfl_xor_sync(0xffffffffu, v, o));
        if (lane == 0) sm[0] = v;
    }
    __syncthreads();
    return sm[0];
}

__device__ __forceinline__ unsigned smem_u32(const void* p) {
    return (unsigned)__cvta_generic_to_shared(p);
}
__device__ __forceinline__ void cpa16(unsigned dst, const void* src, bool ok) {
    int sz = ok ? 16 : 0;
    asm volatile("cp.async.cg.shared.global [%0], [%1], 16, %2;\n"
                 :: "r"(dst), "l"(src), "r"(sz));
}
#define CP_COMMIT asm volatile("cp.async.commit_group;\n")
#define CP_WAIT1  asm volatile("cp.async.wait_group 1;\n")

__device__ __forceinline__ void ldm4(unsigned addr, unsigned* r) {
    asm volatile("ldmatrix.sync.aligned.m8n8.x4.shared.b16 {%0,%1,%2,%3}, [%4];"
        : "=r"(r[0]), "=r"(r[1]), "=r"(r[2]), "=r"(r[3]) : "r"(addr));
}
#define MMA_BF16(d, a, b) asm volatile( \
  "mma.sync.aligned.m16n8k16.row.col.f32.bf16.bf16.f32 " \
  "{%0,%1,%2,%3},{%4,%5,%6,%7},{%8,%9},{%0,%1,%2,%3};\n" \
  : "+f"(d[0]), "+f"(d[1]), "+f"(d[2]), "+f"(d[3]) \
  : "r"(a[0]), "r"(a[1]), "r"(a[2]), "r"(a[3]), "r"(b[0]), "r"(b[1]))

// ---------------- bf16 tensor-core GEMM ----------------
// C = alpha * A @ B^T where A is [M][lda] (k contiguous), B is [N][ldb] (k contiguous).
// 128 x BN x 32 tiles, 3-stage cp.async pipeline, ldmatrix fragments.
// EPI: 0 = fp32 out, 1 = bf16 out.
// limMode: 0 none, 1 clamp K to row-block prefix bound (P@V), 2 skip if col0>=bound (QK^T).
template<int BN, int EPI>
__global__ __launch_bounds__(256, 2) void gemm_bf(
    const bf16* __restrict__ A, const bf16* __restrict__ B0,
    const bf16* __restrict__ B1, const bf16* __restrict__ B2,
    float* __restrict__ Cf, bf16* __restrict__ Cb,
    int M, int N, int K, int lda, int ldb, int ldc,
    long long sA0, long long sA1, long long sB0, long long sB1,
    long long sC0, long long sC1, int hdiv, float alpha, int limMode)
{
    constexpr int BM = 128, BK = 32;
    constexpr int NI = BN / 16;               // n-tiles per warp
    constexpr int RSB = 80;                   // smem row stride bytes (32 bf16 + 8 pad)
    constexpr int ABYTES = BM * RSB;
    constexpr int BBYTES = BN * RSB;
    constexpr int STG = ABYTES + BBYTES;

    const int z = blockIdx.z;
    const int zb = z / hdiv, zh = z - zb * hdiv;
    const bf16* Bp;
    if (B1) Bp = (z == 0) ? B0 : ((z == 1) ? B1 : B2);
    else    Bp = B0 + zb * sB0 + (long long)zh * sB1;
    A += zb * sA0 + (long long)zh * sA1;
    const long long coff = zb * sC0 + (long long)zh * sC1;

    const int row0 = blockIdx.y * BM, col0 = blockIdx.x * BN;

    int Kend = K;
    if (limMode) {
        int lr = min(row0 + BM - 1, M - 1);
        int s, pp; scale_of(lr, s, pp);
        int Lmax = c_bound[s + 1];
        if (limMode == 2 && col0 >= Lmax) return;
        if (limMode == 1) Kend = min(K, Lmax);
    }

    extern __shared__ char smdyn[];
    const unsigned sbase = smem_u32(smdyn);
    const int tid = threadIdx.x, lane = tid & 31, warp = tid >> 5;
    const int wm = warp >> 1, wn = warp & 1;

    auto issue = [&](int it, int buf) {
        const int k0 = it * BK;
        const unsigned as = sbase + buf * STG;
        const unsigned bs = as + ABYTES;
        #pragma unroll
        for (int i = 0; i < 2; i++) {                 // A: 512 chunks
            int c = tid + i * 256;
            int r = c >> 2, kc = c & 3;
            int gk = k0 + kc * 8;
            bool ok = (row0 + r < M) && (gk < Kend);
            const bf16* src = ok ? (A + (size_t)(row0 + r) * lda + gk) : A;
            cpa16(as + r * RSB + kc * 16, src, ok);
        }
        constexpr int BCH = BN * 4;
        #pragma unroll
        for (int i = 0; i < (BCH + 255) / 256; i++) { // B: BN*4 chunks
            int c = tid + i * 256;
            if (c < BCH) {
                int r = c >> 2, kc = c & 3;
                int gk = k0 + kc * 8;
                bool ok = (col0 + r < N) && (gk < Kend);
                const bf16* src = ok ? (Bp + (size_t)(col0 + r) * ldb + gk) : Bp;
                cpa16(bs + r * RSB + kc * 16, src, ok);
            }
        }
    };

    float acc[2][NI][4] = {};
    const int nIter = (Kend + BK - 1) / BK;

    issue(0, 0); CP_COMMIT;
    issue(1, 1); CP_COMMIT;

    const unsigned foff = (unsigned)((lane & 15) * RSB + (lane >> 4) * 16);
    const int gr = lane >> 2, gc = lane & 3;

    for (int it = 0; it < nIter; it++) {
        CP_WAIT1;
        __syncthreads();
        if (it + 2 < nIter) issue(it + 2, (it + 2) % 3);
        CP_COMMIT;
        const unsigned as = sbase + (it % 3) * STG;
        const unsigned bs = as + ABYTES;
        #pragma unroll
        for (int ks = 0; ks < 2; ks++) {
            unsigned ra[2][4];
            #pragma unroll
            for (int mi = 0; mi < 2; mi++)
                ldm4(as + (wm * 32 + mi * 16) * RSB + ks * 32 + foff, ra[mi]);
            unsigned rb[NI][2];
            #pragma unroll
            for (int nj = 0; nj < NI / 2; nj++) {
                unsigned t[4];
                ldm4(bs + (wn * (BN / 2) + nj * 16) * RSB + ks * 32 + foff, t);
                rb[nj * 2][0] = t[0]; rb[nj * 2 + 1][0] = t[1];
                rb[nj * 2][1] = t[2]; rb[nj * 2 + 1][1] = t[3];
            }
            #pragma unroll
            for (int mi = 0; mi < 2; mi++)
                #pragma unroll
                for (int ni = 0; ni < NI; ni++)
                    MMA_BF16(acc[mi][ni], ra[mi], rb[ni]);
        }
    }

    // epilogue
    #pragma unroll
    for (int mi = 0; mi < 2; mi++) {
        #pragma unroll
        for (int ni = 0; ni < NI; ni++) {
            int c = col0 + wn * (BN / 2) + ni * 8 + gc * 2;
            #pragma unroll
            for (int rr = 0; rr < 2; rr++) {
                int r = row0 + wm * 32 + mi * 16 + gr + rr * 8;
                if (r < M) {
                    long long base = coff + (long long)r * ldc + c;
                    float v0 = alpha * acc[mi][ni][rr * 2];
                    float v1 = alpha * acc[mi][ni][rr * 2 + 1];
                    if (EPI == 0) {
                        if (c < N)     Cf[base]     = v0;
                        if (c + 1 < N) Cf[base + 1] = v1;
                    } else {
                        if (c < N)     Cb[base]     = __float2bfloat16(v0);
                        if (c + 1 < N) Cb[base + 1] = __float2bfloat16(v1);
                    }
                }
            }
        }
    }
}

// ---------------- fused SwiGLU FFN GEMM: out = silu(A@w1^T) * (A@w3^T), bf16 ----------------
__global__ __launch_bounds__(256, 2) void gemm_ffn(
    const bf16* __restrict__ A, const bf16* __restrict__ W1, const bf16* __restrict__ W3,
    bf16* __restrict__ C, int M, int N, int K)
{
    constexpr int BM = 128, BN = 64, BK = 32, RSB = 80;
    constexpr int ABYTES = BM * RSB, BBYTES = BN * RSB;
    constexpr int STG = ABYTES + 2 * BBYTES;

    const int row0 = blockIdx.y * BM, col0 = blockIdx.x * BN;
    extern __shared__ char smdyn[];
    const unsigned sbase = smem_u32(smdyn);
    const int tid = threadIdx.x, lane = tid & 31, warp = tid >> 5;
    const int wm = warp >> 1, wn = warp & 1;

    auto issue = [&](int it, int buf) {
        const int k0 = it * BK;
        const unsigned as = sbase + buf * STG;
        const unsigned b1s = as + ABYTES, b3s = b1s + BBYTES;
        #pragma unroll
        for (int i = 0; i < 2; i++) {
            int c = tid + i * 256;
            int r = c >> 2, kc = c & 3;
            int gk = k0 + kc * 8;
            bool ok = (row0 + r < M) && (gk < K);
            cpa16(as + r * RSB + kc * 16, ok ? A + (size_t)(row0 + r) * K + gk : A, ok);
        }
        {
            int r = tid >> 2, kc = tid & 3;
            int gk = k0 + kc * 8;
            bool ok = (col0 + r < N) && (gk < K);
            cpa16(b1s + r * RSB + kc * 16, ok ? W1 + (size_t)(col0 + r) * K + gk : W1, ok);
            cpa16(b3s + r * RSB + kc * 16, ok ? W3 + (size_t)(col0 + r) * K + gk : W3, ok);
        }
    };

    float acc1[2][4][4] = {}, acc3[2][4][4] = {};
    const int nIter = (K + BK - 1) / BK;
    issue(0, 0); CP_COMMIT;
    issue(1, 1); CP_COMMIT;

    const unsigned foff = (unsigned)((lane & 15) * RSB + (lane >> 4) * 16);
    const int gr = lane >> 2, gc = lane & 3;

    for (int it = 0; it < nIter; it++) {
        CP_WAIT1;
        __syncthreads();
        if (it + 2 < nIter) issue(it + 2, (it + 2) % 3);
        CP_COMMIT;
        const unsigned as = sbase + (it % 3) * STG;
        const unsigned b1s = as + ABYTES, b3s = b1s + BBYTES;
        #pragma unroll
        for (int ks = 0; ks < 2; ks++) {
            unsigned ra[2][4];
            #pragma unroll
            for (int mi = 0; mi < 2; mi++)
                ldm4(as + (wm * 32 + mi * 16) * RSB + ks * 32 + foff, ra[mi]);
            unsigned r1[4][2], r3[4][2];
            #pragma unroll
            for (int nj = 0; nj < 2; nj++) {
                unsigned t[4];
                ldm4(b1s + (wn * 32 + nj * 16) * RSB + ks * 32 + foff, t);
                r1[nj * 2][0] = t[0]; r1[nj * 2 + 1][0] = t[1];
                r1[nj * 2][1] = t[2]; r1[nj * 2 + 1][1] = t[3];
                ldm4(b3s + (wn * 32 + nj * 16) * RSB + ks * 32 + foff, t);
                r3[nj * 2][0] = t[0]; r3[nj * 2 + 1][0] = t[1];
                r3[nj * 2][1] = t[2]; r3[nj * 2 + 1][1] = t[3];
            }
            #pragma unroll
            for (int mi = 0; mi < 2; mi++)
                #pragma unroll
                for (int ni = 0; ni < 4; ni++) {
                    MMA_BF16(acc1[mi][ni], ra[mi], r1[ni]);
                    MMA_BF16(acc3[mi][ni], ra[mi], r3[ni]);
                }
        }
    }

    #pragma unroll
    for (int mi = 0; mi < 2; mi++)
        #pragma unroll
        for (int ni = 0; ni < 4; ni++) {
            int c = col0 + wn * 32 + ni * 8 + gc * 2;
            #pragma unroll
            for (int rr = 0; rr < 2; rr++) {
                int r = row0 + wm * 32 + mi * 16 + gr + rr * 8;
                if (r < M && c + 1 < N + 1) {
                    float x0 = acc1[mi][ni][rr * 2],     y0 = acc3[mi][ni][rr * 2];
                    float x1 = acc1[mi][ni][rr * 2 + 1], y1 = acc3[mi][ni][rr * 2 + 1];
                    float g0 = x0 / (1.f + expf(-x0)) * y0;
                    float g1 = x1 / (1.f + expf(-x1)) * y1;
                    size_t base = (size_t)r * N + c;
                    C[base]     = __float2bfloat16(g0);
                    C[base + 1] = __float2bfloat16(g1);
                }
            }
        }
}

// ---------------- conversion / transpose kernels ----------------
// dst[z][C][R] (bf16) = transpose(src[z][R][C] fp32)
__global__ void k_trans(const float* __restrict__ src, bf16* __restrict__ dst,
                        int R, int C, long long sS, long long sD) {
    __shared__ float t[32][33];
    const float* s = src + blockIdx.z * sS;
    bf16* d = dst + blockIdx.z * sD;
    int c0 = blockIdx.x * 32, r0 = blockIdx.y * 32;
    int tx = threadIdx.x, ty = threadIdx.y;
    #pragma unroll
    for (int j = 0; j < 4; j++) {
        int r = r0 + ty + j * 8;
        t[ty + j * 8][tx] = (r < R && c0 + tx < C) ? s[(size_t)r * C + c0 + tx] : 0.f;
    }
    __syncthreads();
    #pragma unroll
    for (int j = 0; j < 4; j++) {
        int c = c0 + ty + j * 8, r = r0 + tx;
        if (c < C && r < R) d[(size_t)c * R + r] = __float2bfloat16(t[tx][ty + j * 8]);
    }
}

__global__ void k_cvt(const float* __restrict__ s, bf16* __restrict__ d, long long n) {
    long long i = (long long)blockIdx.x * blockDim.x + threadIdx.x;
    if (i < n) d[i] = __float2bfloat16(s[i]);
}

// transpose V slab (fp32 [T][D] per b) into g_vt bf16 [b][D][LDT], zero-padding t in [T, LDT)
__global__ void k_vt() {
    __shared__ float t[32][33];
    int b = blockIdx.z;
    const float* s = g_qkv + 2LL * BT_ * D_ + (long long)b * T_ * D_;
    bf16* d = g_vt + (size_t)b * D_ * LDT;
    int t0 = blockIdx.x * 32, d0 = blockIdx.y * 32;
    int tx = threadIdx.x, ty = threadIdx.y;
    #pragma unroll
    for (int j = 0; j < 4; j++) {
        int tt = t0 + ty + j * 8;
        t[ty + j * 8][tx] = (tt < T_) ? s[(size_t)tt * D_ + d0 + tx] : 0.f;
    }
    __syncthreads();
    #pragma unroll
    for (int j = 0; j < 4; j++) {
        int dd = d0 + ty + j * 8, tt = t0 + tx;
        if (tt < LDT) d[(size_t)dd * LDT + tt] = __float2bfloat16(t[tx][ty + j * 8]);
    }
}

// ---------------- small kernels ----------------
__global__ void k_static() {
    int t = blockIdx.x, d = threadIdx.x;
    int s, p; scale_of(t, s, p);
    if (d == 0) g_scl[t] = s;
    int i = d & 31;
    float inv = powf(10000.f, -(float)(2 * i) / 64.f);
    float ang = (float)p * inv;
    g_cos[t * 64 + d] = cosf(ang);
    g_sin[t * 64 + d] = sinf(ang);
}

__global__ void k_tokens(const int* i0, const int* i1, const int* i2,
                         const int* i3, const int* i4, const int* i5) {
    int idx = blockIdx.x * blockDim.x + threadIdx.x;
    if (idx >= BT_) return;
    int b = idx / T_, t = idx - b * T_;
    int s, p; scale_of(t, s, p);
    const int* arr[6] = {i0, i1, i2, i3, i4, i5};
    int sz = 1 << (2 * s);
    g_tok[idx] = arr[s][b * sz + p];
}

__global__ void k_embed(const float* __restrict__ E, const float* __restrict__ SE,
                        const float* __restrict__ start) {
    int row = blockIdx.x;
    int t = row % T_;
    int s = g_scl[t];
    const float* src = (t == 0) ? start : (E + (long long)g_tok[row] * D_);
    const float* se = SE + s * D_;
    float* hp = g_h + (size_t)row * D_;
    bf16* hb = g_hb + (size_t)row * D_;
    for (int d = threadIdx.x; d < D_; d += blockDim.x) {
        float x = src[d] + se[d];
        hp[d] = x;
        hb[d] = __float2bfloat16(x);
    }
}

// per-head RMSNorm + RoPE on q,k (fp32 in, bf16 out). grid = BT*H, block = 64.
__global__ void k_qkrope(const float* __restrict__ qn, const float* __restrict__ kn) {
    int idx = blockIdx.x;
    int head = idx % H_, row = idx / H_;
    int t = row % T_;
    int lane = threadIdx.x & 31;
    bool isK = (threadIdx.x >= 32);
    const float* x = g_qkv + (isK ? (long long)BT_ * D_ : 0) + (size_t)row * D_ + head * DH_;
    bf16* out = (isK ? g_kb : g_qb) + (size_t)row * D_ + head * DH_;
    const float* g = isK ? kn : qn;
    float x1 = x[lane], x2 = x[lane + 32];
    float ss = x1 * x1 + x2 * x2;
    #pragma unroll
    for (int o = 16; o; o >>= 1) ss += __shfl_xor_sync(0xffffffffu, ss, o);
    float r = rsqrtf(ss / 64.f + 1e-6f);
    float y1 = x1 * r * g[lane];
    float y2 = x2 * r * g[lane + 32];
    float c1 = g_cos[t * 64 + lane],      s1 = g_sin[t * 64 + lane];
    float c2 = g_cos[t * 64 + lane + 32], s2 = g_sin[t * 64 + lane + 32];
    out[lane]      = __float2bfloat16(y1 * c1 - y2 * s1);
    out[lane + 32] = __float2bfloat16(y2 * c2 + y1 * s2);
}

// softmax over prefix Li (fp32 in, bf16 out); zero-fill [Li, ceil8(Lz)) so 16B
// cp.async chunks crossing the prefix bound in P@V read only defined zeros.
__global__ void k_softmax() {
    int r = blockIdx.x;
    int i = r % T_;
    const float* row = g_att + (size_t)r * LDT;
    bf16* rob = g_attb + (size_t)r * LDT;
    int Li = c_bound[g_scl[i] + 1];
    int blast = min((i >> 7) * 128 + 127, T_ - 1);
    int Lz = c_bound[g_scl[blast] + 1];
    int Lz8 = (Lz + 7) & ~7;

    float m = -FLT_MAX;
    for (int j = threadIdx.x; j < Li; j += blockDim.x) m = fmaxf(m, row[j]);
    m = blockReduceMax(m);

    float s = 0.f;
    for (int j = threadIdx.x; j < Li; j += blockDim.x) s += expf(row[j] - m);
    s = blockReduceSum(s);
    float inv = 1.f / s;
    for (int j = threadIdx.x; j < Li; j += blockDim.x)
        rob[j] = __float2bfloat16(expf(row[j] - m) * inv);
    for (int j = Li + threadIdx.x; j < Lz8; j += blockDim.x)
        rob[j] = __float2bfloat16(0.f);
}

// h = RMSNorm(h + delta) * gain; also writes bf16 copy
__global__ void k_rms(float* __restrict__ h, const float* __restrict__ delta,
                      const float* __restrict__ gain) {
    int row = blockIdx.x;
    float* hp = h + (size_t)row * D_;
    bf16* hb = g_hb + (size_t)row * D_;
    const float* dp = delta + (size_t)row * D_;
    float ss = 0.f;
    for (int d = threadIdx.x; d < D_; d += blockDim.x) {
        float x = hp[d] + dp[d];
        ss += x * x;
    }
    ss = blockReduceSum(ss);
    float r = rsqrtf(ss / (float)D_ + 1e-6f);
    for (int d = threadIdx.x; d < D_; d += blockDim.x) {
        float x = (hp[d] + dp[d]) * r * gain[d];
        hp[d] = x;
        hb[d] = __float2bfloat16(x);
    }
}

__global__ void k_loss_row() {
    int row = blockIdx.x;
    const float* lp = g_logits + (size_t)row * V_;
    float m = -FLT_MAX;
    for (int j = threadIdx.x; j < V_; j += blockDim.x) m = fmaxf(m, lp[j]);
    m = blockReduceMax(m);
    float s = 0.f;
    for (int j = threadIdx.x; j < V_; j += blockDim.x) s += expf(lp[j] - m);
    s = blockReduceSum(s);
    if (threadIdx.x == 0) {
        float lse = m + logf(s);
        g_ce[row] = lse - lp[g_tok[row]];
        g_zl[row] = lse * lse;
    }
}

__global__ void k_loss_final(float* out) {
    float s1 = 0.f, s2 = 0.f;
    for (int j = threadIdx.x; j < BT_; j += blockDim.x) { s1 += g_ce[j]; s2 += g_zl[j]; }
    s1 = blockReduceSum(s1);
    s2 = blockReduceSum(s2);
    if (threadIdx.x == 0) out[0] = s1 / (float)BT_ + ZLOSSW * (s2 / (float)BT_);
}

// ---------------- entry point ----------------
extern "C" void kernel_launch(void* const* d_in, const int* in_sizes, int n_in,
                              void* d_out, int out_size) {
    const int* i0 = (const int*)d_in[0];
    const int* i1 = (const int*)d_in[1];
    const int* i2 = (const int*)d_in[2];
    const int* i3 = (const int*)d_in[3];
    const int* i4 = (const int*)d_in[4];
    const int* i5 = (const int*)d_in[5];
    const float* token_embed = (const float*)d_in[6];
    const float* scale_embed = (const float*)d_in[7];
    const float* start_token = (const float*)d_in[8];
    const float* wq = (const float*)d_in[9];
    const float* wk = (const float*)d_in[10];
    const float* wv = (const float*)d_in[11];
    const float* wo = (const float*)d_in[12];
    const float* qn = (const float*)d_in[13];
    const float* kn = (const float*)d_in[14];
    const float* n1 = (const float*)d_in[15];
    const float* n2 = (const float*)d_in[16];
    const float* w1 = (const float*)d_in[17];
    const float* w3 = (const float*)d_in[18];
    const float* w2 = (const float*)d_in[19];

    cudaFuncSetAttribute((const void*)gemm_bf<128, 0>,
                         cudaFuncAttributeMaxDynamicSharedMemorySize, 61440);
    cudaFuncSetAttribute((const void*)gemm_bf<64, 1>,
                         cudaFuncAttributeMaxDynamicSharedMemorySize, 46080);
    cudaFuncSetAttribute((const void*)gemm_ffn,
                         cudaFuncAttributeMaxDynamicSharedMemorySize, 61440);

    void* p;
    cudaGetSymbolAddress(&p, g_h);      float* h    = (float*)p;
    cudaGetSymbolAddress(&p, g_qkv);    float* qkvf = (float*)p;
    cudaGetSymbolAddress(&p, g_tmp);    float* tmp  = (float*)p;
    cudaGetSymbolAddress(&p, g_att);    float* att  = (float*)p;
    cudaGetSymbolAddress(&p, g_logits); float* lg   = (float*)p;
    cudaGetSymbolAddress(&p, g_hb);     bf16* hb    = (bf16*)p;
    cudaGetSymbolAddress(&p, g_qb);     bf16* qb    = (bf16*)p;
    cudaGetSymbolAddress(&p, g_kb);     bf16* kb    = (bf16*)p;
    cudaGetSymbolAddress(&p, g_vt);     bf16* vt    = (bf16*)p;
    cudaGetSymbolAddress(&p, g_ob);     bf16* ob    = (bf16*)p;
    cudaGetSymbolAddress(&p, g_attb);   bf16* attb  = (bf16*)p;
    cudaGetSymbolAddress(&p, g_ggb);    bf16* ggb   = (bf16*)p;
    cudaGetSymbolAddress(&p, g_wqt);    bf16* wqt   = (bf16*)p;
    cudaGetSymbolAddress(&p, g_wkt);    bf16* wkt   = (bf16*)p;
    cudaGetSymbolAddress(&p, g_wvt);    bf16* wvt   = (bf16*)p;
    cudaGetSymbolAddress(&p, g_wot);    bf16* wot   = (bf16*)p;
    cudaGetSymbolAddress(&p, g_w1t);    bf16* w1t   = (bf16*)p;
    cudaGetSymbolAddress(&p, g_w3t);    bf16* w3t   = (bf16*)p;
    cudaGetSymbolAddress(&p, g_w2t);    bf16* w2t   = (bf16*)p;
    cudaGetSymbolAddress(&p, g_embb);   bf16* embb  = (bf16*)p;

    const long long DD = (long long)D_ * D_;
    const long long DF = (long long)D_ * DFF_;

    // weight conversion + transpose (every call; deterministic)
    dim3 tb(32, 8);
    k_trans<<<dim3(32, 32, NL_), tb>>>(wq, wqt, D_, D_, DD, DD);
    k_trans<<<dim3(32, 32, NL_), tb>>>(wk, wkt, D_, D_, DD, DD);
    k_trans<<<dim3(32, 32, NL_), tb>>>(wv, wvt, D_, D_, DD, DD);
    k_trans<<<dim3(32, 32, NL_), tb>>>(wo, wot, D_, D_, DD, DD);
    k_trans<<<dim3(86, 32, NL_), tb>>>(w1, w1t, D_, DFF_, DF, DF);
    k_trans<<<dim3(86, 32, NL_), tb>>>(w3, w3t, D_, DFF_, DF, DF);
    k_trans<<<dim3(32, 86, NL_), tb>>>(w2, w2t, DFF_, D_, DF, DF);
    k_cvt<<<(V_ * D_ + 255) / 256, 256>>>(token_embed, embb, (long long)V_ * D_);

    // static tables + embeddings
    k_static<<<T_, 64>>>();
    k_tokens<<<(BT_ + 255) / 256, 256>>>(i0, i1, i2, i3, i4, i5);
    k_embed<<<BT_, 256>>>(token_embed, scale_embed, start_token);

    const long long TD = (long long)T_ * D_;
    const long long TL = (long long)T_ * LDT;

    for (int l = 0; l < NL_; l++) {
        // fused qkv → fp32 slabs
        gemm_bf<128, 0><<<dim3(8, 22, 3), 256, 61440>>>(
            hb, wqt + l * DD, wkt + l * DD, wvt + l * DD, qkvf, nullptr,
            BT_, D_, D_, D_, D_, D_,
            0, 0, 0, 0, (long long)BT_ * D_, 0, 1, 1.f, 0);

        k_qkrope<<<BT_ * H_, 64>>>(qn + l * DH_, kn + l * DH_);
        k_vt<<<dim3(43, 32, B_), tb>>>();

        // scores = q @ k^T / 8 (fp32, padded rows), block-skip past prefix bound
        gemm_bf<128, 0><<<dim3(11, 11, 32), 256, 61440>>>(
            qb, kb, nullptr, nullptr, att, nullptr,
            T_, T_, DH_, D_, D_, LDT,
            TD, DH_, TD, DH_,
            (long long)H_ * TL, TL, H_, 0.125f, 2);

        k_softmax<<<B_ * H_ * T_, 256>>>();

        // o = P @ V (bf16 probs x bf16 V^T), K clamped to prefix bound, bf16 out
        gemm_bf<64, 1><<<dim3(1, 11, 32), 256, 46080>>>(
            attb, vt, nullptr, nullptr, nullptr, ob,
            T_, DH_, T_, LDT, LDT, D_,
            (long long)H_ * TL, TL,
            (long long)D_ * LDT, (long long)DH_ * LDT,
            TD, DH_, H_, 1.f, 1);

        // attn output projection
        gemm_bf<128, 0><<<dim3(8, 22, 1), 256, 61440>>>(
            ob, wot + l * DD, nullptr, nullptr, tmp, nullptr,
            BT_, D_, D_, D_, D_, D_,
            0, 0, 0, 0, 0, 0, 1, 1.f, 0);

        k_rms<<<BT_, 256>>>(h, tmp, n1 + l * D_);

        // fused SwiGLU
        gemm_ffn<<<dim3(43, 22, 1), 256, 61440>>>(
            hb, w1t + l * DF, w3t + l * DF, ggb, BT_, DFF_, D_);

        // down projection
        gemm_bf<128, 0><<<dim3(8, 22, 1), 256, 61440>>>(
            ggb, w2t + l * DF, nullptr, nullptr, tmp, nullptr,
            BT_, D_, DFF_, DFF_, DFF_, D_,
            0, 0, 0, 0, 0, 0, 1, 1.f, 0);

        k_rms<<<BT_, 256>>>(h, tmp, n2 + l * D_);
    }

    // logits = h @ token_embed^T
    gemm_bf<128, 0><<<dim3(32, 22, 1), 256, 61440>>>(
        hb, embb, nullptr, nullptr, lg, nullptr,
        BT_, V_, D_, D_, D_, V_,
        0, 0, 0, 0, 0, 0, 1, 1.f, 0);

    // loss
    k_loss_row<<<BT_, 256>>>();
    k_loss_final<<<1, 256>>>((float*)d_out);
}

// round 5
// speedup vs baseline: 8.2999x; 1.4466x over previous
#include <cuda_runtime.h>
#include <cuda_bf16.h>
#include <math.h>
#include <float.h>

// ---------------- problem constants ----------------
#define V_  4096
#define D_  1024
#define H_  16
#define DH_ 64
#define NL_ 12
#define DFF_ 2752
#define B_  2
#define T_  1365
#define BT_ (B_*T_)          // 2730
#define ZLOSSW 1e-4f

typedef __nv_bfloat16 bf16;

__device__ __constant__ int c_bound[7] = {0, 1, 5, 21, 85, 341, 1365};

// ---------------- scratch (static device globals) ----------------
__device__ float g_h[BT_ * D_];
__device__ float g_qkv[3 * BT_ * D_];
__device__ float g_tmp[BT_ * D_];
__device__ float g_logits[(size_t)BT_ * V_];
__device__ float g_ce[BT_];
__device__ float g_zl[BT_];
__device__ int   g_tok[BT_];
__device__ int   g_scl[T_];
__device__ float g_cos[T_ * DH_];
__device__ float g_sin[T_ * DH_];

// bf16 operands
__device__ bf16 g_hb[BT_ * D_];
__device__ bf16 g_qb[BT_ * D_];
__device__ bf16 g_kb[BT_ * D_];
__device__ bf16 g_vb[BT_ * D_];
__device__ bf16 g_ob[BT_ * D_];
__device__ bf16 g_ggb[(size_t)BT_ * DFF_];
// transposed bf16 weights ([N][K] layout for the GEMM B operand)
__device__ bf16 g_wqt[NL_ * D_ * D_];
__device__ bf16 g_wkt[NL_ * D_ * D_];
__device__ bf16 g_wvt[NL_ * D_ * D_];
__device__ bf16 g_wot[NL_ * D_ * D_];
__device__ bf16 g_w1t[(size_t)NL_ * DFF_ * D_];
__device__ bf16 g_w3t[(size_t)NL_ * DFF_ * D_];
__device__ bf16 g_w2t[(size_t)NL_ * D_ * DFF_];
__device__ bf16 g_embb[V_ * D_];

// ---------------- helpers ----------------
__device__ __forceinline__ void scale_of(int t, int& s, int& p) {
    if (t < 1)        { s = 0; p = t; }
    else if (t < 5)   { s = 1; p = t - 1; }
    else if (t < 21)  { s = 2; p = t - 5; }
    else if (t < 85)  { s = 3; p = t - 21; }
    else if (t < 341) { s = 4; p = t - 85; }
    else              { s = 5; p = t - 341; }
}

__device__ __forceinline__ float blockReduceSum(float v) {
    __shared__ float sm[32];
    __syncthreads();
    int lane = threadIdx.x & 31, w = threadIdx.x >> 5;
    #pragma unroll
    for (int o = 16; o; o >>= 1) v += __shfl_xor_sync(0xffffffffu, v, o);
    if (lane == 0) sm[w] = v;
    __syncthreads();
    int nw = (blockDim.x + 31) >> 5;
    v = (threadIdx.x < nw) ? sm[threadIdx.x] : 0.f;
    if (w == 0) {
        #pragma unroll
        for (int o = 16; o; o >>= 1) v += __shfl_xor_sync(0xffffffffu, v, o);
        if (lane == 0) sm[0] = v;
    }
    __syncthreads();
    return sm[0];
}

__device__ __forceinline__ float blockReduceMax(float v) {
    __shared__ float sm[32];
    __syncthreads();
    int lane = threadIdx.x & 31, w = threadIdx.x >> 5;
    #pragma unroll
    for (int o = 16; o; o >>= 1) v = fmaxf(v, __shfl_xor_sync(0xffffffffu, v, o));
    if (lane == 0) sm[w] = v;
    __syncthreads();
    int nw = (blockDim.x + 31) >> 5;
    v = (threadIdx.x < nw) ? sm[threadIdx.x] : -FLT_MAX;
    if (w == 0) {
        #pragma unroll
        for (int o = 16; o; o >>= 1) v = fmaxf(v, __shfl_xor_sync(0xffffffffu, v, o));
        if (lane == 0) sm[0] = v;
    }
    __syncthreads();
    return sm[0];
}

__device__ __forceinline__ unsigned smem_u32(const void* p) {
    return (unsigned)__cvta_generic_to_shared(p);
}
__device__ __forceinline__ void cpa16(unsigned dst, const void* src, bool ok) {
    int sz = ok ? 16 : 0;
    asm volatile("cp.async.cg.shared.global [%0], [%1], 16, %2;\n"
                 :: "r"(dst), "l"(src), "r"(sz));
}
#define CP_COMMIT   asm volatile("cp.async.commit_group;\n")
#define CP_WAITG(N) asm volatile("cp.async.wait_group %0;\n" :: "n"(N))

__device__ __forceinline__ void ldm4(unsigned addr, unsigned* r) {
    asm volatile("ldmatrix.sync.aligned.m8n8.x4.shared.b16 {%0,%1,%2,%3}, [%4];"
        : "=r"(r[0]), "=r"(r[1]), "=r"(r[2]), "=r"(r[3]) : "r"(addr));
}
__device__ __forceinline__ void ldm4t(unsigned addr, unsigned* r) {
    asm volatile("ldmatrix.sync.aligned.m8n8.x4.trans.shared.b16 {%0,%1,%2,%3}, [%4];"
        : "=r"(r[0]), "=r"(r[1]), "=r"(r[2]), "=r"(r[3]) : "r"(addr));
}
__device__ __forceinline__ unsigned packbf2(float lo, float hi) {
    unsigned r;
    asm("cvt.rn.bf16x2.f32 %0, %1, %2;" : "=r"(r) : "f"(hi), "f"(lo));
    return r;
}
#define MMA_BF16(d, a, b) asm volatile( \
  "mma.sync.aligned.m16n8k16.row.col.f32.bf16.bf16.f32 " \
  "{%0,%1,%2,%3},{%4,%5,%6,%7},{%8,%9},{%0,%1,%2,%3};\n" \
  : "+f"(d[0]), "+f"(d[1]), "+f"(d[2]), "+f"(d[3]) \
  : "r"(a[0]), "r"(a[1]), "r"(a[2]), "r"(a[3]), "r"(b[0]), "r"(b[1]))

// ---------------- bf16 tensor-core GEMM (4-stage cp.async pipeline) ----------------
// C = alpha * A @ B^T; A [M][lda] k-contig, B [N][ldb] k-contig.
// 128 x 128 x 32 tiles, 256 threads (8 warps, 4Mx2N).
template<int BN, int EPI>
__global__ __launch_bounds__(256, 2) void gemm_bf(
    const bf16* __restrict__ A, const bf16* __restrict__ B0,
    const bf16* __restrict__ B1, const bf16* __restrict__ B2,
    float* __restrict__ Cf, bf16* __restrict__ Cb,
    int M, int N, int K, int lda, int ldb, int ldc,
    long long sC0, float alpha)
{
    constexpr int BM = 128, BK = 32;
    constexpr int NI = BN / 16;
    constexpr int RSB = 80;
    constexpr int ABYTES = BM * RSB;
    constexpr int BBYTES = BN * RSB;
    constexpr int STG = ABYTES + BBYTES;
    constexpr int NSTG = 4;

    const int z = blockIdx.z;
    const bf16* Bp;
    if (B1) Bp = (z == 0) ? B0 : ((z == 1) ? B1 : B2);
    else    Bp = B0;
    const long long coff = (long long)z * sC0;

    const int row0 = blockIdx.y * BM, col0 = blockIdx.x * BN;

    extern __shared__ char smdyn[];
    const unsigned sbase = smem_u32(smdyn);
    const int tid = threadIdx.x, lane = tid & 31, warp = tid >> 5;
    const int wm = warp >> 1, wn = warp & 1;

    auto issue = [&](int it, int buf) {
        const int k0 = it * BK;
        const unsigned as = sbase + buf * STG;
        const unsigned bs = as + ABYTES;
        #pragma unroll
        for (int i = 0; i < 2; i++) {
            int c = tid + i * 256;
            int r = c >> 2, kc = c & 3;
            int gk = k0 + kc * 8;
            bool ok = (row0 + r < M) && (gk < K);
            const bf16* src = ok ? (A + (size_t)(row0 + r) * lda + gk) : A;
            cpa16(as + r * RSB + kc * 16, src, ok);
        }
        constexpr int BCH = BN * 4;
        #pragma unroll
        for (int i = 0; i < (BCH + 255) / 256; i++) {
            int c = tid + i * 256;
            if (c < BCH) {
                int r = c >> 2, kc = c & 3;
                int gk = k0 + kc * 8;
                bool ok = (col0 + r < N) && (gk < K);
                const bf16* src = ok ? (Bp + (size_t)(col0 + r) * ldb + gk) : Bp;
                cpa16(bs + r * RSB + kc * 16, src, ok);
            }
        }
    };

    float acc[2][NI][4] = {};
    const int nIter = (K + BK - 1) / BK;

    issue(0, 0); CP_COMMIT;
    issue(1, 1); CP_COMMIT;
    issue(2, 2); CP_COMMIT;

    const unsigned foff = (unsigned)((lane & 15) * RSB + (lane >> 4) * 16);
    const int gr = lane >> 2, gc = lane & 3;

    for (int it = 0; it < nIter; it++) {
        CP_WAITG(2);
        __syncthreads();
        if (it + 3 < nIter) issue(it + 3, (it + 3) % NSTG);
        CP_COMMIT;
        const unsigned as = sbase + (it % NSTG) * STG;
        const unsigned bs = as + ABYTES;
        #pragma unroll
        for (int ks = 0; ks < 2; ks++) {
            unsigned ra[2][4];
            #pragma unroll
            for (int mi = 0; mi < 2; mi++)
                ldm4(as + (wm * 32 + mi * 16) * RSB + ks * 32 + foff, ra[mi]);
            unsigned rb[NI][2];
            #pragma unroll
            for (int nj = 0; nj < NI / 2; nj++) {
                unsigned t[4];
                ldm4(bs + (wn * (BN / 2) + nj * 16) * RSB + ks * 32 + foff, t);
                rb[nj * 2][0] = t[0]; rb[nj * 2 + 1][0] = t[1];
                rb[nj * 2][1] = t[2]; rb[nj * 2 + 1][1] = t[3];
            }
            #pragma unroll
            for (int mi = 0; mi < 2; mi++)
                #pragma unroll
                for (int ni = 0; ni < NI; ni++)
                    MMA_BF16(acc[mi][ni], ra[mi], rb[ni]);
        }
        __syncthreads();
    }

    #pragma unroll
    for (int mi = 0; mi < 2; mi++) {
        #pragma unroll
        for (int ni = 0; ni < NI; ni++) {
            int c = col0 + wn * (BN / 2) + ni * 8 + gc * 2;
            #pragma unroll
            for (int rr = 0; rr < 2; rr++) {
                int r = row0 + wm * 32 + mi * 16 + gr + rr * 8;
                if (r < M) {
                    long long base = coff + (long long)r * ldc + c;
                    float v0 = alpha * acc[mi][ni][rr * 2];
                    float v1 = alpha * acc[mi][ni][rr * 2 + 1];
                    if (EPI == 0) {
                        if (c < N)     Cf[base]     = v0;
                        if (c + 1 < N) Cf[base + 1] = v1;
                    } else {
                        if (c < N)     Cb[base]     = __float2bfloat16(v0);
                        if (c + 1 < N) Cb[base + 1] = __float2bfloat16(v1);
                    }
                }
            }
        }
    }
}

// ---------------- fused SwiGLU FFN GEMM (4 stages) ----------------
__global__ __launch_bounds__(256, 2) void gemm_ffn(
    const bf16* __restrict__ A, const bf16* __restrict__ W1, const bf16* __restrict__ W3,
    bf16* __restrict__ C, int M, int N, int K)
{
    constexpr int BM = 128, BN = 64, BK = 32, RSB = 80;
    constexpr int ABYTES = BM * RSB, BBYTES = BN * RSB;
    constexpr int STG = ABYTES + 2 * BBYTES;
    constexpr int NSTG = 4;

    const int row0 = blockIdx.y * BM, col0 = blockIdx.x * BN;
    extern __shared__ char smdyn[];
    const unsigned sbase = smem_u32(smdyn);
    const int tid = threadIdx.x, lane = tid & 31, warp = tid >> 5;
    const int wm = warp >> 1, wn = warp & 1;

    auto issue = [&](int it, int buf) {
        const int k0 = it * BK;
        const unsigned as = sbase + buf * STG;
        const unsigned b1s = as + ABYTES, b3s = b1s + BBYTES;
        #pragma unroll
        for (int i = 0; i < 2; i++) {
            int c = tid + i * 256;
            int r = c >> 2, kc = c & 3;
            int gk = k0 + kc * 8;
            bool ok = (row0 + r < M) && (gk < K);
            cpa16(as + r * RSB + kc * 16, ok ? A + (size_t)(row0 + r) * K + gk : A, ok);
        }
        {
            int r = tid >> 2, kc = tid & 3;
            int gk = k0 + kc * 8;
            bool ok = (col0 + r < N) && (gk < K);
            cpa16(b1s + r * RSB + kc * 16, ok ? W1 + (size_t)(col0 + r) * K + gk : W1, ok);
            cpa16(b3s + r * RSB + kc * 16, ok ? W3 + (size_t)(col0 + r) * K + gk : W3, ok);
        }
    };

    float acc1[2][4][4] = {}, acc3[2][4][4] = {};
    const int nIter = (K + BK - 1) / BK;
    issue(0, 0); CP_COMMIT;
    issue(1, 1); CP_COMMIT;
    issue(2, 2); CP_COMMIT;

    const unsigned foff = (unsigned)((lane & 15) * RSB + (lane >> 4) * 16);
    const int gr = lane >> 2, gc = lane & 3;

    for (int it = 0; it < nIter; it++) {
        CP_WAITG(2);
        __syncthreads();
        if (it + 3 < nIter) issue(it + 3, (it + 3) % NSTG);
        CP_COMMIT;
        const unsigned as = sbase + (it % NSTG) * STG;
        const unsigned b1s = as + ABYTES, b3s = b1s + BBYTES;
        #pragma unroll
        for (int ks = 0; ks < 2; ks++) {
            unsigned ra[2][4];
            #pragma unroll
            for (int mi = 0; mi < 2; mi++)
                ldm4(as + (wm * 32 + mi * 16) * RSB + ks * 32 + foff, ra[mi]);
            unsigned r1[4][2], r3[4][2];
            #pragma unroll
            for (int nj = 0; nj < 2; nj++) {
                unsigned t[4];
                ldm4(b1s + (wn * 32 + nj * 16) * RSB + ks * 32 + foff, t);
                r1[nj * 2][0] = t[0]; r1[nj * 2 + 1][0] = t[1];
                r1[nj * 2][1] = t[2]; r1[nj * 2 + 1][1] = t[3];
                ldm4(b3s + (wn * 32 + nj * 16) * RSB + ks * 32 + foff, t);
                r3[nj * 2][0] = t[0]; r3[nj * 2 + 1][0] = t[1];
                r3[nj * 2][1] = t[2]; r3[nj * 2 + 1][1] = t[3];
            }
            #pragma unroll
            for (int mi = 0; mi < 2; mi++)
                #pragma unroll
                for (int ni = 0; ni < 4; ni++) {
                    MMA_BF16(acc1[mi][ni], ra[mi], r1[ni]);
                    MMA_BF16(acc3[mi][ni], ra[mi], r3[ni]);
                }
        }
        __syncthreads();
    }

    #pragma unroll
    for (int mi = 0; mi < 2; mi++)
        #pragma unroll
        for (int ni = 0; ni < 4; ni++) {
            int c = col0 + wn * 32 + ni * 8 + gc * 2;
            #pragma unroll
            for (int rr = 0; rr < 2; rr++) {
                int r = row0 + wm * 32 + mi * 16 + gr + rr * 8;
                if (r < M) {
                    float x0 = acc1[mi][ni][rr * 2],     y0 = acc3[mi][ni][rr * 2];
                    float x1 = acc1[mi][ni][rr * 2 + 1], y1 = acc3[mi][ni][rr * 2 + 1];
                    float g0 = x0 / (1.f + expf(-x0)) * y0;
                    float g1 = x1 / (1.f + expf(-x1)) * y1;
                    size_t base = (size_t)r * N + c;
                    C[base]     = __float2bfloat16(g0);
                    C[base + 1] = __float2bfloat16(g1);
                }
            }
        }
}

// ---------------- fused flash attention (prefix-masked, online softmax) ----------------
// grid = (ceil(T/128), B*H), 256 threads (8 warps, each owns 16 query rows).
#define FL_ROWB 144   // 64 bf16 + 8 pad = 72 bf16 = 144 bytes per row
__global__ __launch_bounds__(256, 1) void k_flash() {
    extern __shared__ char smdyn[];
    const unsigned uQ = smem_u32(smdyn);
    const unsigned uK = uQ + 128 * FL_ROWB;
    const unsigned uV = uK + 2 * 128 * FL_ROWB;

    const int z = blockIdx.y;
    const int b = z >> 4, h = z & 15;
    const int row0 = blockIdx.x * 128;
    const int tid = threadIdx.x, lane = tid & 31, warp = tid >> 5;

    int sl, pl; scale_of(min(row0 + 127, T_ - 1), sl, pl);
    const int Lmax = c_bound[sl + 1];
    const int nkb = (Lmax + 127) >> 7;

    const size_t hoff = ((size_t)b * T_) * D_ + h * DH_;
    const bf16* qg = g_qb + hoff;
    const bf16* kg = g_kb + hoff;
    const bf16* vg = g_vb + hoff;
    bf16* og = g_ob + hoff;

    const int lr = tid >> 1, lc0 = (tid & 1) * 4;
    {   // Q tile
        bool ok = (row0 + lr) < T_;
        const bf16* s = qg + (size_t)(row0 + lr) * D_ + lc0 * 8;
        #pragma unroll
        for (int j = 0; j < 4; j++) cpa16(uQ + lr * FL_ROWB + (lc0 + j) * 16, s + j * 8, ok);
    }
    auto issueKV = [&](int kb, int buf) {
        int jr = kb * 128 + lr;
        bool ok = jr < T_;
        const bf16* sk = kg + (size_t)jr * D_ + lc0 * 8;
        const bf16* sv = vg + (size_t)jr * D_ + lc0 * 8;
        unsigned off = buf * (128 * FL_ROWB) + lr * FL_ROWB + lc0 * 16;
        #pragma unroll
        for (int j = 0; j < 4; j++) {
            cpa16(uK + off + j * 16, sk + j * 8, ok);
            cpa16(uV + off + j * 16, sv + j * 8, ok);
        }
    };
    issueKV(0, 0); CP_COMMIT;
    if (nkb > 1) issueKV(1, 1);
    CP_COMMIT;
    CP_WAITG(1);
    __syncthreads();

    const unsigned foff = (unsigned)((lane & 15) * FL_ROWB + (lane >> 4) * 16);
    unsigned aq[4][4];
    #pragma unroll
    for (int ks = 0; ks < 4; ks++)
        ldm4(uQ + (warp * 16) * FL_ROWB + ks * 32 + foff, aq[ks]);

    const int gr = lane >> 2, gc = lane & 3;
    const int r0g = row0 + warp * 16 + gr;
    int Li0 = 0, Li1 = 0;
    if (r0g < T_)     { int s2, p2; scale_of(r0g, s2, p2);     Li0 = c_bound[s2 + 1]; }
    if (r0g + 8 < T_) { int s2, p2; scale_of(r0g + 8, s2, p2); Li1 = c_bound[s2 + 1]; }

    float m0 = -1e30f, m1 = -1e30f, l0 = 0.f, l1 = 0.f;
    float oacc[8][4] = {};
    const float ALPHA = 0.125f * 1.4426950408889634f;   // 1/sqrt(64) * log2(e)

    for (int kb = 0; kb < nkb; kb++) {
        const unsigned bK = uK + (kb & 1) * (128 * FL_ROWB);
        const unsigned bV = uV + (kb & 1) * (128 * FL_ROWB);

        // S = Q @ K^T (16 rows x 128 keys per warp)
        float s[16][4];
        #pragma unroll
        for (int i = 0; i < 16; i++) { s[i][0] = s[i][1] = s[i][2] = s[i][3] = 0.f; }
        #pragma unroll
        for (int ks = 0; ks < 4; ks++) {
            #pragma unroll
            for (int n2 = 0; n2 < 8; n2++) {
                unsigned t[4];
                ldm4(bK + (n2 * 16) * FL_ROWB + ks * 32 + foff, t);
                unsigned b0[2] = {t[0], t[2]}, b1[2] = {t[1], t[3]};
                MMA_BF16(s[n2 * 2],     aq[ks], b0);
                MMA_BF16(s[n2 * 2 + 1], aq[ks], b1);
            }
        }
        // prefix mask + scale (base-2 domain)
        const int j0 = kb * 128;
        float mx0 = -1e30f, mx1 = -1e30f;
        #pragma unroll
        for (int ni = 0; ni < 16; ni++) {
            int jc = j0 + ni * 8 + 2 * gc;
            s[ni][0] = (jc     < Li0) ? s[ni][0] * ALPHA : -1e30f;
            s[ni][1] = (jc + 1 < Li0) ? s[ni][1] * ALPHA : -1e30f;
            s[ni][2] = (jc     < Li1) ? s[ni][2] * ALPHA : -1e30f;
            s[ni][3] = (jc + 1 < Li1) ? s[ni][3] * ALPHA : -1e30f;
            mx0 = fmaxf(mx0, fmaxf(s[ni][0], s[ni][1]));
            mx1 = fmaxf(mx1, fmaxf(s[ni][2], s[ni][3]));
        }
        mx0 = fmaxf(mx0, __shfl_xor_sync(0xffffffffu, mx0, 1));
        mx0 = fmaxf(mx0, __shfl_xor_sync(0xffffffffu, mx0, 2));
        mx1 = fmaxf(mx1, __shfl_xor_sync(0xffffffffu, mx1, 1));
        mx1 = fmaxf(mx1, __shfl_xor_sync(0xffffffffu, mx1, 2));
        float mn0 = fmaxf(m0, mx0), mn1 = fmaxf(m1, mx1);
        float r0 = exp2f(m0 - mn0), r1 = exp2f(m1 - mn1);
        float sum0 = 0.f, sum1 = 0.f;
        #pragma unroll
        for (int ni = 0; ni < 16; ni++) {
            float p0 = exp2f(s[ni][0] - mn0); s[ni][0] = p0; sum0 += p0;
            float p1 = exp2f(s[ni][1] - mn0); s[ni][1] = p1; sum0 += p1;
            float p2 = exp2f(s[ni][2] - mn1); s[ni][2] = p2; sum1 += p2;
            float p3 = exp2f(s[ni][3] - mn1); s[ni][3] = p3; sum1 += p3;
        }
        sum0 += __shfl_xor_sync(0xffffffffu, sum0, 1);
        sum0 += __shfl_xor_sync(0xffffffffu, sum0, 2);
        sum1 += __shfl_xor_sync(0xffffffffu, sum1, 1);
        sum1 += __shfl_xor_sync(0xffffffffu, sum1, 2);
        l0 = l0 * r0 + sum0; l1 = l1 * r1 + sum1;
        m0 = mn0; m1 = mn1;
        #pragma unroll
        for (int t8 = 0; t8 < 8; t8++) {
            oacc[t8][0] *= r0; oacc[t8][1] *= r0;
            oacc[t8][2] *= r1; oacc[t8][3] *= r1;
        }
        // O += P @ V (V fragments via ldmatrix.trans of row-major V tile)
        #pragma unroll
        for (int j = 0; j < 8; j++) {
            unsigned pa[4];
            pa[0] = packbf2(s[2 * j][0],     s[2 * j][1]);
            pa[1] = packbf2(s[2 * j][2],     s[2 * j][3]);
            pa[2] = packbf2(s[2 * j + 1][0], s[2 * j + 1][1]);
            pa[3] = packbf2(s[2 * j + 1][2], s[2 * j + 1][3]);
            unsigned vrow = bV + (j * 16 + (lane & 7) + 8 * ((lane >> 3) & 1)) * FL_ROWB
                               + (lane >> 4) * 16;
            #pragma unroll
            for (int d2 = 0; d2 < 4; d2++) {
                unsigned t[4];
                ldm4t(vrow + d2 * 32, t);
                unsigned vb0[2] = {t[0], t[1]}, vb1[2] = {t[2], t[3]};
                MMA_BF16(oacc[d2 * 2],     pa, vb0);
                MMA_BF16(oacc[d2 * 2 + 1], pa, vb1);
            }
        }
        __syncthreads();
        if (kb + 2 < nkb) issueKV(kb + 2, kb & 1);
        CP_COMMIT;
        CP_WAITG(1);
        __syncthreads();
    }

    float li0 = 1.f / l0, li1 = 1.f / l1;
    #pragma unroll
    for (int t8 = 0; t8 < 8; t8++) {
        int c = t8 * 8 + 2 * gc;
        if (r0g < T_) {
            og[(size_t)r0g * D_ + c]     = __float2bfloat16(oacc[t8][0] * li0);
            og[(size_t)r0g * D_ + c + 1] = __float2bfloat16(oacc[t8][1] * li0);
        }
        if (r0g + 8 < T_) {
            og[(size_t)(r0g + 8) * D_ + c]     = __float2bfloat16(oacc[t8][2] * li1);
            og[(size_t)(r0g + 8) * D_ + c + 1] = __float2bfloat16(oacc[t8][3] * li1);
        }
    }
}

// ---------------- conversion / transpose kernels ----------------
__global__ void k_trans(const float* __restrict__ src, bf16* __restrict__ dst,
                        int R, int C, long long sS, long long sD) {
    __shared__ float t[32][33];
    const float* s = src + blockIdx.z * sS;
    bf16* d = dst + blockIdx.z * sD;
    int c0 = blockIdx.x * 32, r0 = blockIdx.y * 32;
    int tx = threadIdx.x, ty = threadIdx.y;
    #pragma unroll
    for (int j = 0; j < 4; j++) {
        int r = r0 + ty + j * 8;
        t[ty + j * 8][tx] = (r < R && c0 + tx < C) ? s[(size_t)r * C + c0 + tx] : 0.f;
    }
    __syncthreads();
    #pragma unroll
    for (int j = 0; j < 4; j++) {
        int c = c0 + ty + j * 8, r = r0 + tx;
        if (c < C && r < R) d[(size_t)c * R + r] = __float2bfloat16(t[tx][ty + j * 8]);
    }
}

__global__ void k_cvt(const float* __restrict__ s, bf16* __restrict__ d, long long n) {
    long long i = (long long)blockIdx.x * blockDim.x + threadIdx.x;
    if (i < n) d[i] = __float2bfloat16(s[i]);
}

// ---------------- small kernels ----------------
__global__ void k_static() {
    int t = blockIdx.x, d = threadIdx.x;
    int s, p; scale_of(t, s, p);
    if (d == 0) g_scl[t] = s;
    int i = d & 31;
    float inv = powf(10000.f, -(float)(2 * i) / 64.f);
    float ang = (float)p * inv;
    g_cos[t * 64 + d] = cosf(ang);
    g_sin[t * 64 + d] = sinf(ang);
}

__global__ void k_tokens(const int* i0, const int* i1, const int* i2,
                         const int* i3, const int* i4, const int* i5) {
    int idx = blockIdx.x * blockDim.x + threadIdx.x;
    if (idx >= BT_) return;
    int b = idx / T_, t = idx - b * T_;
    int s, p; scale_of(t, s, p);
    const int* arr[6] = {i0, i1, i2, i3, i4, i5};
    int sz = 1 << (2 * s);
    g_tok[idx] = arr[s][b * sz + p];
}

__global__ void k_embed(const float* __restrict__ E, const float* __restrict__ SE,
                        const float* __restrict__ start) {
    int row = blockIdx.x;
    int t = row % T_;
    int s = g_scl[t];
    const float* src = (t == 0) ? start : (E + (long long)g_tok[row] * D_);
    const float* se = SE + s * D_;
    float* hp = g_h + (size_t)row * D_;
    bf16* hb = g_hb + (size_t)row * D_;
    for (int d = threadIdx.x; d < D_; d += blockDim.x) {
        float x = src[d] + se[d];
        hp[d] = x;
        hb[d] = __float2bfloat16(x);
    }
}

// per-head RMSNorm + RoPE on q,k (fp32 in, bf16 out), plus V bf16 convert.
__global__ void k_qkrope(const float* __restrict__ qn, const float* __restrict__ kn) {
    int idx = blockIdx.x;
    int head = idx % H_, row = idx / H_;
    int t = row % T_;
    int lane = threadIdx.x & 31;
    bool isK = (threadIdx.x >= 32);
    const float* x = g_qkv + (isK ? (long long)BT_ * D_ : 0) + (size_t)row * D_ + head * DH_;
    bf16* out = (isK ? g_kb : g_qb) + (size_t)row * D_ + head * DH_;
    const float* g = isK ? kn : qn;
    float x1 = x[lane], x2 = x[lane + 32];
    float ss = x1 * x1 + x2 * x2;
    #pragma unroll
    for (int o = 16; o; o >>= 1) ss += __shfl_xor_sync(0xffffffffu, ss, o);
    float r = rsqrtf(ss / 64.f + 1e-6f);
    float y1 = x1 * r * g[lane];
    float y2 = x2 * r * g[lane + 32];
    float c1 = g_cos[t * 64 + lane],      s1 = g_sin[t * 64 + lane];
    float c2 = g_cos[t * 64 + lane + 32], s2 = g_sin[t * 64 + lane + 32];
    out[lane]      = __float2bfloat16(y1 * c1 - y2 * s1);
    out[lane + 32] = __float2bfloat16(y2 * c2 + y1 * s2);
    // V convert (all 64 threads)
    const float* vf = g_qkv + 2LL * BT_ * D_ + (size_t)row * D_ + head * DH_;
    bf16* vo = g_vb + (size_t)row * D_ + head * DH_;
    vo[threadIdx.x] = __float2bfloat16(vf[threadIdx.x]);
}

__global__ void k_rms(float* __restrict__ h, const float* __restrict__ delta,
                      const float* __restrict__ gain) {
    int row = blockIdx.x;
    float* hp = h + (size_t)row * D_;
    bf16* hb = g_hb + (size_t)row * D_;
    const float* dp = delta + (size_t)row * D_;
    float ss = 0.f;
    for (int d = threadIdx.x; d < D_; d += blockDim.x) {
        float x = hp[d] + dp[d];
        ss += x * x;
    }
    ss = blockReduceSum(ss);
    float r = rsqrtf(ss / (float)D_ + 1e-6f);
    for (int d = threadIdx.x; d < D_; d += blockDim.x) {
        float x = (hp[d] + dp[d]) * r * gain[d];
        hp[d] = x;
        hb[d] = __float2bfloat16(x);
    }
}

__global__ void k_loss_row() {
    int row = blockIdx.x;
    const float* lp = g_logits + (size_t)row * V_;
    float m = -FLT_MAX;
    for (int j = threadIdx.x; j < V_; j += blockDim.x) m = fmaxf(m, lp[j]);
    m = blockReduceMax(m);
    float s = 0.f;
    for (int j = threadIdx.x; j < V_; j += blockDim.x) s += expf(lp[j] - m);
    s = blockReduceSum(s);
    if (threadIdx.x == 0) {
        float lse = m + logf(s);
        g_ce[row] = lse - lp[g_tok[row]];
        g_zl[row] = lse * lse;
    }
}

__global__ void k_loss_final(float* out) {
    float s1 = 0.f, s2 = 0.f;
    for (int j = threadIdx.x; j < BT_; j += blockDim.x) { s1 += g_ce[j]; s2 += g_zl[j]; }
    s1 = blockReduceSum(s1);
    s2 = blockReduceSum(s2);
    if (threadIdx.x == 0) out[0] = s1 / (float)BT_ + ZLOSSW * (s2 / (float)BT_);
}

// ---------------- entry point ----------------
extern "C" void kernel_launch(void* const* d_in, const int* in_sizes, int n_in,
                              void* d_out, int out_size) {
    const int* i0 = (const int*)d_in[0];
    const int* i1 = (const int*)d_in[1];
    const int* i2 = (const int*)d_in[2];
    const int* i3 = (const int*)d_in[3];
    const int* i4 = (const int*)d_in[4];
    const int* i5 = (const int*)d_in[5];
    const float* token_embed = (const float*)d_in[6];
    const float* scale_embed = (const float*)d_in[7];
    const float* start_token = (const float*)d_in[8];
    const float* wq = (const float*)d_in[9];
    const float* wk = (const float*)d_in[10];
    const float* wv = (const float*)d_in[11];
    const float* wo = (const float*)d_in[12];
    const float* qn = (const float*)d_in[13];
    const float* kn = (const float*)d_in[14];
    const float* n1 = (const float*)d_in[15];
    const float* n2 = (const float*)d_in[16];
    const float* w1 = (const float*)d_in[17];
    const float* w3 = (const float*)d_in[18];
    const float* w2 = (const float*)d_in[19];

    cudaFuncSetAttribute((const void*)gemm_bf<128, 0>,
                         cudaFuncAttributeMaxDynamicSharedMemorySize, 81920);
    cudaFuncSetAttribute((const void*)gemm_ffn,
                         cudaFuncAttributeMaxDynamicSharedMemorySize, 81920);
    cudaFuncSetAttribute((const void*)k_flash,
                         cudaFuncAttributeMaxDynamicSharedMemorySize, 92160);

    void* p;
    cudaGetSymbolAddress(&p, g_h);      float* h    = (float*)p;
    cudaGetSymbolAddress(&p, g_qkv);    float* qkvf = (float*)p;
    cudaGetSymbolAddress(&p, g_tmp);    float* tmp  = (float*)p;
    cudaGetSymbolAddress(&p, g_logits); float* lg   = (float*)p;
    cudaGetSymbolAddress(&p, g_hb);     bf16* hb    = (bf16*)p;
    cudaGetSymbolAddress(&p, g_ob);     bf16* ob    = (bf16*)p;
    cudaGetSymbolAddress(&p, g_ggb);    bf16* ggb   = (bf16*)p;
    cudaGetSymbolAddress(&p, g_wqt);    bf16* wqt   = (bf16*)p;
    cudaGetSymbolAddress(&p, g_wkt);    bf16* wkt   = (bf16*)p;
    cudaGetSymbolAddress(&p, g_wvt);    bf16* wvt   = (bf16*)p;
    cudaGetSymbolAddress(&p, g_wot);    bf16* wot   = (bf16*)p;
    cudaGetSymbolAddress(&p, g_w1t);    bf16* w1t   = (bf16*)p;
    cudaGetSymbolAddress(&p, g_w3t);    bf16* w3t   = (bf16*)p;
    cudaGetSymbolAddress(&p, g_w2t);    bf16* w2t   = (bf16*)p;
    cudaGetSymbolAddress(&p, g_embb);   bf16* embb  = (bf16*)p;

    const long long DD = (long long)D_ * D_;
    const long long DF = (long long)D_ * DFF_;

    // weight conversion + transpose
    dim3 tb(32, 8);
    k_trans<<<dim3(32, 32, NL_), tb>>>(wq, wqt, D_, D_, DD, DD);
    k_trans<<<dim3(32, 32, NL_), tb>>>(wk, wkt, D_, D_, DD, DD);
    k_trans<<<dim3(32, 32, NL_), tb>>>(wv, wvt, D_, D_, DD, DD);
    k_trans<<<dim3(32, 32, NL_), tb>>>(wo, wot, D_, D_, DD, DD);
    k_trans<<<dim3(86, 32, NL_), tb>>>(w1, w1t, D_, DFF_, DF, DF);
    k_trans<<<dim3(86, 32, NL_), tb>>>(w3, w3t, D_, DFF_, DF, DF);
    k_trans<<<dim3(32, 86, NL_), tb>>>(w2, w2t, DFF_, D_, DF, DF);
    k_cvt<<<(V_ * D_ + 255) / 256, 256>>>(token_embed, embb, (long long)V_ * D_);

    // static tables + embeddings
    k_static<<<T_, 64>>>();
    k_tokens<<<(BT_ + 255) / 256, 256>>>(i0, i1, i2, i3, i4, i5);
    k_embed<<<BT_, 256>>>(token_embed, scale_embed, start_token);

    for (int l = 0; l < NL_; l++) {
        // fused qkv → fp32 slabs
        gemm_bf<128, 0><<<dim3(8, 22, 3), 256, 81920>>>(
            hb, wqt + l * DD, wkt + l * DD, wvt + l * DD, qkvf, nullptr,
            BT_, D_, D_, D_, D_, D_, (long long)BT_ * D_, 1.f);

        k_qkrope<<<BT_ * H_, 64>>>(qn + l * DH_, kn + l * DH_);

        // fused attention
        k_flash<<<dim3(11, B_ * H_), 256, 92160>>>();

        // attn output projection
        gemm_bf<128, 0><<<dim3(8, 22, 1), 256, 81920>>>(
            ob, wot + l * DD, nullptr, nullptr, tmp, nullptr,
            BT_, D_, D_, D_, D_, D_, 0, 1.f);

        k_rms<<<BT_, 256>>>(h, tmp, n1 + l * D_);

        // fused SwiGLU
        gemm_ffn<<<dim3(43, 22, 1), 256, 81920>>>(
            hb, w1t + l * DF, w3t + l * DF, ggb, BT_, DFF_, D_);

        // down projection
        gemm_bf<128, 0><<<dim3(8, 22, 1), 256, 81920>>>(
            ggb, w2t + l * DF, nullptr, nullptr, tmp, nullptr,
            BT_, D_, DFF_, DFF_, DFF_, D_, 0, 1.f);

        k_rms<<<BT_, 256>>>(h, tmp, n2 + l * D_);
    }

    // logits = h @ token_embed^T
    gemm_bf<128, 0><<<dim3(32, 22, 1), 256, 81920>>>(
        hb, embb, nullptr, nullptr, lg, nullptr,
        BT_, V_, D_, D_, D_, V_, 0, 1.f);

    // loss
    k_loss_row<<<BT_, 256>>>();
    k_loss_final<<<1, 256>>>((float*)d_out);
}